// round 8
// baseline (speedup 1.0000x reference)
#include <cuda_runtime.h>
#include <cuda_bf16.h>
#include <cstdint>

#define N_NODES 100000
#define N_EDGES 1600000
#define CH 64
#define TCOLS 576               // 9 * 64
#define KDIM 640                // 576 + 64
#define SCAN_B 1024
#define NSCAN_BLOCKS ((N_NODES + SCAN_B - 1) / SCAN_B)   // 98
#define MTILE 128
#define GEMM_GRID ((N_NODES + MTILE - 1) / MTILE)        // 782

struct __align__(16) EdgeRec {   // 64 B
    int src; int pad0; int pad1; int pad2;
    float b[9];
    float pad3; float pad4; float pad5;
};

// ------------------------- device scratch (no allocs) -----------------------
__device__ int     g_idx[2 * N_EDGES];
__device__ int     g_is64;
__device__ int     g_cnt[N_NODES];
__device__ int     g_cur[N_NODES];
__device__ int     g_row[N_NODES + 1];
__device__ int     g_bsum[NSCAN_BLOCKS];
__device__ int     g_boff[NSCAN_BLOCKS];
__device__ EdgeRec g_edges[N_EDGES];
__device__ float   g_t[(size_t)N_NODES * TCOLS];
__device__ float   g_x2[(size_t)N_NODES * CH];
// Transposed split-bf16 weights: [layer][n(out) 64][k 640]
__device__ __nv_bfloat16 g_wthi[2][64 * KDIM];
__device__ __nv_bfloat16 g_wtlo[2][64 * KDIM];

// --------------------------- CSR build --------------------------------------
__global__ void detect_kernel(const int* __restrict__ ei32) {
    int ok = 1;
    for (int i = threadIdx.x * 2 + 1; i < 512; i += 64)
        if (ei32[i] != 0) ok = 0;
    ok = __all_sync(0xffffffffu, ok) ? 1 : 0;
    if (threadIdx.x == 0) g_is64 = ok;
}

__global__ __launch_bounds__(256) void zero_kernel() {
    int i = blockIdx.x * 256 + threadIdx.x;
    if (i < N_NODES) { g_cnt[i] = 0; g_cur[i] = 0; }
}

__global__ __launch_bounds__(256) void convert_hist_kernel(const int* __restrict__ ei32) {
    int j = blockIdx.x * 256 + threadIdx.x;
    if (j >= 2 * N_EDGES) return;
    int is64 = g_is64;
    int v = is64 ? ei32[2 * j] : ei32[j];
    v = ((unsigned)v < (unsigned)N_NODES) ? v : 0;
    g_idx[j] = v;
    if (j >= N_EDGES) atomicAdd(&g_cnt[v], 1);
}

__global__ __launch_bounds__(SCAN_B) void scan1_kernel() {
    __shared__ int s[SCAN_B];
    int t = threadIdx.x;
    int i = blockIdx.x * SCAN_B + t;
    int v = (i < N_NODES) ? g_cnt[i] : 0;
    s[t] = v;
    __syncthreads();
    for (int off = 1; off < SCAN_B; off <<= 1) {
        int tmp = (t >= off) ? s[t - off] : 0;
        __syncthreads();
        s[t] += tmp;
        __syncthreads();
    }
    if (i < N_NODES) g_row[i] = s[t] - v;
    if (t == SCAN_B - 1) g_bsum[blockIdx.x] = s[t];
}

__global__ void scan2_kernel() {
    int run = 0;
    for (int b = 0; b < NSCAN_BLOCKS; b++) { g_boff[b] = run; run += g_bsum[b]; }
    g_row[N_NODES] = N_EDGES;
}

__global__ __launch_bounds__(256) void scan3_kernel() {
    int i = blockIdx.x * 256 + threadIdx.x;
    if (i < N_NODES) g_row[i] += g_boff[i >> 10];
}

__global__ __launch_bounds__(256) void scatter_kernel(const float* __restrict__ pseudo) {
    int e = blockIdx.x * 256 + threadIdx.x;
    if (e >= N_EDGES) return;
    int src = g_idx[e];
    int dst = g_idx[N_EDGES + e];
    float2 p = ((const float2*)pseudo)[e];
    float u = p.x, v = p.y;
    float bu0 = 0.5f * u * u - u + 0.5f, bu1 = -u * u + u + 0.5f, bu2 = 0.5f * u * u;
    float bv0 = 0.5f * v * v - v + 0.5f, bv1 = -v * v + v + 0.5f, bv2 = 0.5f * v * v;

    int pos = g_row[dst] + atomicAdd(&g_cur[dst], 1);
    float4* q = (float4*)&g_edges[pos];
    int4 s4 = make_int4(src, 0, 0, 0);
    q[0] = *(float4*)&s4;
    q[1] = make_float4(bu0 * bv0, bu0 * bv1, bu0 * bv2, bu1 * bv0);
    q[2] = make_float4(bu1 * bv1, bu1 * bv2, bu2 * bv0, bu2 * bv1);
    q[3] = make_float4(bu2 * bv2, 0.f, 0.f, 0.f);
}

// --------------------------- Aggregation ------------------------------------
template<bool LAYER2>
__global__ __launch_bounds__(256) void agg_kernel(const float* __restrict__ Xext) {
    const float* X = LAYER2 ? g_x2 : Xext;
    int node = blockIdx.x * 8 + (threadIdx.x >> 5);
    if (node >= N_NODES) return;
    const int lane = threadIdx.x & 31;

    int beg = g_row[node], end = g_row[node + 1];
    float acc[9][2] = {};

    #pragma unroll 2
    for (int e = beg; e < end; e++) {
        const EdgeRec* r = &g_edges[e];
        int src = __ldg(&r->src);
        float4 b03 = __ldg((const float4*)&r->b[0]);
        float4 b47 = __ldg((const float4*)&r->b[4]);
        float  b8  = __ldg(&r->b[8]);
        float2 xv  = __ldg((const float2*)&X[(size_t)src * CH + 2 * lane]);
        acc[0][0] += b03.x * xv.x; acc[0][1] += b03.x * xv.y;
        acc[1][0] += b03.y * xv.x; acc[1][1] += b03.y * xv.y;
        acc[2][0] += b03.z * xv.x; acc[2][1] += b03.z * xv.y;
        acc[3][0] += b03.w * xv.x; acc[3][1] += b03.w * xv.y;
        acc[4][0] += b47.x * xv.x; acc[4][1] += b47.x * xv.y;
        acc[5][0] += b47.y * xv.x; acc[5][1] += b47.y * xv.y;
        acc[6][0] += b47.z * xv.x; acc[6][1] += b47.z * xv.y;
        acc[7][0] += b47.w * xv.x; acc[7][1] += b47.w * xv.y;
        acc[8][0] += b8    * xv.x; acc[8][1] += b8    * xv.y;
    }

    float* tp = g_t + (size_t)node * TCOLS + 2 * lane;
    #pragma unroll
    for (int k = 0; k < 9; k++)
        *(float2*)(tp + k * 64) = make_float2(acc[k][0], acc[k][1]);
}

// --------------------------- Weight prep ------------------------------------
__global__ __launch_bounds__(256) void wprep_kernel(
    int layer, const float* __restrict__ W9, const float* __restrict__ root)
{
    int idx = blockIdx.x * 256 + threadIdx.x;
    if (idx >= 64 * KDIM) return;
    int n = idx / KDIM, k = idx % KDIM;
    float w = (k < TCOLS) ? W9[k * 64 + n] : root[(k - TCOLS) * 64 + n];
    __nv_bfloat16 h = __float2bfloat16(w);
    g_wthi[layer][idx] = h;
    g_wtlo[layer][idx] = __float2bfloat16(w - __bfloat162float(h));
}

// --------------------------- mma.sync GEMM ----------------------------------
// Split a float2 into packed-bf16 hi (mantissa truncation) and lo (residual).
__device__ __forceinline__ void split2(float2 v, uint32_t& hi, uint32_t& lo) {
    uint32_t u0 = __float_as_uint(v.x), u1 = __float_as_uint(v.y);
    asm("prmt.b32 %0, %1, %2, 0x7632;" : "=r"(hi) : "r"(u0), "r"(u1));
    float l0 = v.x - __uint_as_float(u0 & 0xFFFF0000u);
    float l1 = v.y - __uint_as_float(u1 & 0xFFFF0000u);
    asm("cvt.rn.bf16x2.f32 %0, %1, %2;" : "=r"(lo) : "f"(l1), "f"(l0));
}

__device__ __forceinline__ void mma16816(float* c,
    uint32_t a0, uint32_t a1, uint32_t a2, uint32_t a3, uint32_t b0, uint32_t b1)
{
    asm("mma.sync.aligned.m16n8k16.row.col.f32.bf16.bf16.f32 "
        "{%0,%1,%2,%3}, {%4,%5,%6,%7}, {%8,%9}, {%0,%1,%2,%3};"
        : "+f"(c[0]), "+f"(c[1]), "+f"(c[2]), "+f"(c[3])
        : "r"(a0), "r"(a1), "r"(a2), "r"(a3), "r"(b0), "r"(b1));
}

// out[n,c] = relu( bias[c] + [t|X][n,:] @ WT[c,:] ), K=640, M=128/block.
// Warp w: rows mbase + w*16 .. +15. Fragment layout per PTX m16n8k16.
template<bool LAYER2>
__global__ __launch_bounds__(256) void gemm_mma_kernel(
    const float* __restrict__ Xext,
    const float* __restrict__ bias,
    float* __restrict__ Hext)
{
    const float* X = LAYER2 ? g_x2 : Xext;
    float* H = LAYER2 ? Hext : g_x2;
    const __nv_bfloat16* WThi = g_wthi[LAYER2 ? 1 : 0];
    const __nv_bfloat16* WTlo = g_wtlo[LAYER2 ? 1 : 0];

    const int w = threadIdx.x >> 5, l = threadIdx.x & 31;
    const int g = l >> 2;               // group row 0..7
    const int t2 = (l & 3) * 2;         // k/col pair base 0,2,4,6
    const int r0 = blockIdx.x * MTILE + w * 16 + g;
    const int r1 = r0 + 8;
    const bool v0 = r0 < N_NODES, v1 = r1 < N_NODES;

    float acc[8][4] = {};   // 8 n-tiles x {c0,c1,c2,c3}

    #pragma unroll 2
    for (int kc = 0; kc < 40; kc++) {
        const int kb = kc * 16;
        // ---- A fragments: rows r0/r1, cols kb+t2(+1) and kb+t2+8(+1) ----
        float2 x00 = make_float2(0.f, 0.f), x01 = x00, x10 = x00, x11 = x00;
        if (kc < 36) {
            const float* p0 = g_t + (size_t)r0 * TCOLS + kb;
            const float* p1 = g_t + (size_t)r1 * TCOLS + kb;
            if (v0) { x00 = *(const float2*)(p0 + t2); x01 = *(const float2*)(p0 + t2 + 8); }
            if (v1) { x10 = *(const float2*)(p1 + t2); x11 = *(const float2*)(p1 + t2 + 8); }
        } else {
            const int kx = kb - TCOLS;
            const float* p0 = X + (size_t)r0 * CH + kx;
            const float* p1 = X + (size_t)r1 * CH + kx;
            if (v0) { x00 = *(const float2*)(p0 + t2); x01 = *(const float2*)(p0 + t2 + 8); }
            if (v1) { x10 = *(const float2*)(p1 + t2); x11 = *(const float2*)(p1 + t2 + 8); }
        }
        uint32_t ah0, al0, ah1, al1, ah2, al2, ah3, al3;
        split2(x00, ah0, al0);   // reg0: row g,   k lo-half
        split2(x10, ah1, al1);   // reg1: row g+8, k lo-half
        split2(x01, ah2, al2);   // reg2: row g,   k hi-half
        split2(x11, ah3, al3);   // reg3: row g+8, k hi-half

        // ---- per n-tile: B frags from transposed weights, 3 mma terms ----
        #pragma unroll
        for (int nt = 0; nt < 8; nt++) {
            const int n = nt * 8 + g;
            const size_t off = (size_t)n * KDIM + kb + t2;
            uint32_t bh0 = __ldg((const uint32_t*)(WThi + off));
            uint32_t bh1 = __ldg((const uint32_t*)(WThi + off + 8));
            uint32_t bl0 = __ldg((const uint32_t*)(WTlo + off));
            uint32_t bl1 = __ldg((const uint32_t*)(WTlo + off + 8));
            mma16816(acc[nt], ah0, ah1, ah2, ah3, bh0, bh1);
            mma16816(acc[nt], ah0, ah1, ah2, ah3, bl0, bl1);
            mma16816(acc[nt], al0, al1, al2, al3, bh0, bh1);
        }
    }

    // ---- epilogue: bias + relu, c0c1 -> row r0, c2c3 -> row r1 ----
    #pragma unroll
    for (int nt = 0; nt < 8; nt++) {
        const int c = nt * 8 + t2;
        float b0 = __ldg(&bias[c]), b1 = __ldg(&bias[c + 1]);
        if (v0) {
            float2 o = make_float2(fmaxf(acc[nt][0] + b0, 0.f),
                                   fmaxf(acc[nt][1] + b1, 0.f));
            *(float2*)&H[(size_t)r0 * CH + c] = o;
        }
        if (v1) {
            float2 o = make_float2(fmaxf(acc[nt][2] + b0, 0.f),
                                   fmaxf(acc[nt][3] + b1, 0.f));
            *(float2*)&H[(size_t)r1 * CH + c] = o;
        }
    }
}

// ---------------------------------------------------------------------------
extern "C" void kernel_launch(void* const* d_in, const int* in_sizes, int n_in,
                              void* d_out, int out_size) {
    const float* x      = (const float*)d_in[0];
    const int* ei32     = (const int*)d_in[1];
    const float* pseudo = (const float*)d_in[2];
    const float* W1     = (const float*)d_in[3];
    const float* root1  = (const float*)d_in[4];
    const float* b1     = (const float*)d_in[5];
    const float* W2     = (const float*)d_in[6];
    const float* root2  = (const float*)d_in[7];
    const float* b2     = (const float*)d_in[8];
    float* out          = (float*)d_out;

    // ---- CSR build + weight prep (shared by both layers) ----
    detect_kernel<<<1, 32>>>(ei32);
    zero_kernel<<<(N_NODES + 255) / 256, 256>>>();
    convert_hist_kernel<<<(2 * N_EDGES + 255) / 256, 256>>>(ei32);
    scan1_kernel<<<NSCAN_BLOCKS, SCAN_B>>>();
    scan2_kernel<<<1, 1>>>();
    scan3_kernel<<<(N_NODES + 255) / 256, 256>>>();
    scatter_kernel<<<(N_EDGES + 255) / 256, 256>>>(pseudo);
    wprep_kernel<<<(64 * KDIM + 255) / 256, 256>>>(0, W1, root1);
    wprep_kernel<<<(64 * KDIM + 255) / 256, 256>>>(1, W2, root2);

    const int agg_grid = (N_NODES + 7) / 8;

    // ---- layer 1 ----
    agg_kernel<false><<<agg_grid, 256>>>(x);
    gemm_mma_kernel<false><<<GEMM_GRID, 256>>>(x, b1, nullptr);

    // ---- layer 2 ----
    agg_kernel<true><<<agg_grid, 256>>>(nullptr);
    gemm_mma_kernel<true><<<GEMM_GRID, 256>>>(nullptr, b2, out);
}

// round 9
// speedup vs baseline: 1.4016x; 1.4016x over previous
#include <cuda_runtime.h>
#include <cuda_bf16.h>
#include <cstdint>

#define N_NODES 100000
#define N_EDGES 1600000
#define CH 64
#define TCOLS 576               // 9 * 64
#define KDIM 640                // 576 + 64
#define SCAN_B 1024
#define NSCAN_BLOCKS ((N_NODES + SCAN_B - 1) / SCAN_B)   // 98
#define MTILE 128
#define GEMM_GRID ((N_NODES + MTILE - 1) / MTILE)        // 782
#define NKC 40                  // K16 steps
#define NFRAG (NKC * 8 * 32)    // 10240 uint4 per layer

struct __align__(16) EdgeRec {   // 64 B
    int src; int pad0; int pad1; int pad2;
    float b[9];
    float pad3; float pad4; float pad5;
};

// ------------------------- device scratch (no allocs) -----------------------
__device__ int     g_idx[2 * N_EDGES];
__device__ int     g_is64;
__device__ int     g_cnt[N_NODES];
__device__ int     g_cur[N_NODES];
__device__ int     g_row[N_NODES + 1];
__device__ int     g_bsum[NSCAN_BLOCKS];
__device__ int     g_boff[NSCAN_BLOCKS];
__device__ EdgeRec g_edges[N_EDGES];
__device__ float   g_t[(size_t)N_NODES * TCOLS];
__device__ float   g_x2[(size_t)N_NODES * CH];
// Fragment-ready split-bf16 weights: [layer][kc][nt][lane] = {bh0,bh1,bl0,bl1}
__device__ uint4   g_wfrag[2][NFRAG];

// --------------------------- CSR build --------------------------------------
__global__ void detect_kernel(const int* __restrict__ ei32) {
    int ok = 1;
    for (int i = threadIdx.x * 2 + 1; i < 512; i += 64)
        if (ei32[i] != 0) ok = 0;
    ok = __all_sync(0xffffffffu, ok) ? 1 : 0;
    if (threadIdx.x == 0) g_is64 = ok;
}

__global__ __launch_bounds__(256) void zero_kernel() {
    int i = blockIdx.x * 256 + threadIdx.x;
    if (i < N_NODES) { g_cnt[i] = 0; g_cur[i] = 0; }
}

__global__ __launch_bounds__(256) void convert_hist_kernel(const int* __restrict__ ei32) {
    int j = blockIdx.x * 256 + threadIdx.x;
    if (j >= 2 * N_EDGES) return;
    int is64 = g_is64;
    int v = is64 ? ei32[2 * j] : ei32[j];
    v = ((unsigned)v < (unsigned)N_NODES) ? v : 0;
    g_idx[j] = v;
    if (j >= N_EDGES) atomicAdd(&g_cnt[v], 1);
}

__global__ __launch_bounds__(SCAN_B) void scan1_kernel() {
    __shared__ int s[SCAN_B];
    int t = threadIdx.x;
    int i = blockIdx.x * SCAN_B + t;
    int v = (i < N_NODES) ? g_cnt[i] : 0;
    s[t] = v;
    __syncthreads();
    for (int off = 1; off < SCAN_B; off <<= 1) {
        int tmp = (t >= off) ? s[t - off] : 0;
        __syncthreads();
        s[t] += tmp;
        __syncthreads();
    }
    if (i < N_NODES) g_row[i] = s[t] - v;
    if (t == SCAN_B - 1) g_bsum[blockIdx.x] = s[t];
}

__global__ void scan2_kernel() {
    int run = 0;
    for (int b = 0; b < NSCAN_BLOCKS; b++) { g_boff[b] = run; run += g_bsum[b]; }
    g_row[N_NODES] = N_EDGES;
}

__global__ __launch_bounds__(256) void scan3_kernel() {
    int i = blockIdx.x * 256 + threadIdx.x;
    if (i < N_NODES) g_row[i] += g_boff[i >> 10];
}

__global__ __launch_bounds__(256) void scatter_kernel(const float* __restrict__ pseudo) {
    int e = blockIdx.x * 256 + threadIdx.x;
    if (e >= N_EDGES) return;
    int src = g_idx[e];
    int dst = g_idx[N_EDGES + e];
    float2 p = ((const float2*)pseudo)[e];
    float u = p.x, v = p.y;
    float bu0 = 0.5f * u * u - u + 0.5f, bu1 = -u * u + u + 0.5f, bu2 = 0.5f * u * u;
    float bv0 = 0.5f * v * v - v + 0.5f, bv1 = -v * v + v + 0.5f, bv2 = 0.5f * v * v;

    int pos = g_row[dst] + atomicAdd(&g_cur[dst], 1);
    float4* q = (float4*)&g_edges[pos];
    int4 s4 = make_int4(src, 0, 0, 0);
    q[0] = *(float4*)&s4;
    q[1] = make_float4(bu0 * bv0, bu0 * bv1, bu0 * bv2, bu1 * bv0);
    q[2] = make_float4(bu1 * bv1, bu1 * bv2, bu2 * bv0, bu2 * bv1);
    q[3] = make_float4(bu2 * bv2, 0.f, 0.f, 0.f);
}

// --------------------------- Aggregation ------------------------------------
template<bool LAYER2>
__global__ __launch_bounds__(256) void agg_kernel(const float* __restrict__ Xext) {
    const float* X = LAYER2 ? g_x2 : Xext;
    int node = blockIdx.x * 8 + (threadIdx.x >> 5);
    if (node >= N_NODES) return;
    const int lane = threadIdx.x & 31;

    int beg = g_row[node], end = g_row[node + 1];
    float acc[9][2] = {};

    #pragma unroll 2
    for (int e = beg; e < end; e++) {
        const EdgeRec* r = &g_edges[e];
        int src = __ldg(&r->src);
        float4 b03 = __ldg((const float4*)&r->b[0]);
        float4 b47 = __ldg((const float4*)&r->b[4]);
        float  b8  = __ldg(&r->b[8]);
        float2 xv  = __ldg((const float2*)&X[(size_t)src * CH + 2 * lane]);
        acc[0][0] += b03.x * xv.x; acc[0][1] += b03.x * xv.y;
        acc[1][0] += b03.y * xv.x; acc[1][1] += b03.y * xv.y;
        acc[2][0] += b03.z * xv.x; acc[2][1] += b03.z * xv.y;
        acc[3][0] += b03.w * xv.x; acc[3][1] += b03.w * xv.y;
        acc[4][0] += b47.x * xv.x; acc[4][1] += b47.x * xv.y;
        acc[5][0] += b47.y * xv.x; acc[5][1] += b47.y * xv.y;
        acc[6][0] += b47.z * xv.x; acc[6][1] += b47.z * xv.y;
        acc[7][0] += b47.w * xv.x; acc[7][1] += b47.w * xv.y;
        acc[8][0] += b8    * xv.x; acc[8][1] += b8    * xv.y;
    }

    float* tp = g_t + (size_t)node * TCOLS + 2 * lane;
    #pragma unroll
    for (int k = 0; k < 9; k++)
        *(float2*)(tp + k * 64) = make_float2(acc[k][0], acc[k][1]);
}

// ------------------- Weight prep: fragment-ready table -----------------------
__device__ __forceinline__ uint32_t packbf2(float a, float b) {
    __nv_bfloat162 h;
    h.x = __float2bfloat16(a);  // low  = first element (smaller k)
    h.y = __float2bfloat16(b);
    return *(uint32_t*)&h;
}

__global__ __launch_bounds__(256) void wprep_kernel(
    int layer, const float* __restrict__ W9, const float* __restrict__ root)
{
    int idx = blockIdx.x * 256 + threadIdx.x;
    if (idx >= NFRAG) return;
    int l  = idx & 31;
    int nt = (idx >> 5) & 7;
    int kc = idx >> 8;
    int g = l >> 2, t2 = (l & 3) * 2;
    int n = nt * 8 + g;
    int k0 = kc * 16 + t2;

    float w[4];   // k0, k0+1, k0+8, k0+9
    #pragma unroll
    for (int j = 0; j < 4; j++) {
        int kk = k0 + (j & 1) + (j >> 1) * 8;
        w[j] = (kk < TCOLS) ? W9[kk * 64 + n] : root[(kk - TCOLS) * 64 + n];
    }
    uint32_t bh0 = packbf2(w[0], w[1]);
    uint32_t bh1 = packbf2(w[2], w[3]);
    __nv_bfloat162* h0 = (__nv_bfloat162*)&bh0;
    __nv_bfloat162* h1 = (__nv_bfloat162*)&bh1;
    uint32_t bl0 = packbf2(w[0] - __bfloat162float(h0->x), w[1] - __bfloat162float(h0->y));
    uint32_t bl1 = packbf2(w[2] - __bfloat162float(h1->x), w[3] - __bfloat162float(h1->y));
    g_wfrag[layer][idx] = make_uint4(bh0, bh1, bl0, bl1);
}

// --------------------------- mma.sync GEMM ----------------------------------
// hi = mantissa truncation of (x,y) packed bf16x2; lo = residual (rn).
__device__ __forceinline__ void split2(float x, float y, uint32_t& hi, uint32_t& lo) {
    uint32_t u0 = __float_as_uint(x), u1 = __float_as_uint(y);
    asm("prmt.b32 %0, %1, %2, 0x7632;" : "=r"(hi) : "r"(u0), "r"(u1));
    float l0 = x - __uint_as_float(u0 & 0xFFFF0000u);
    float l1 = y - __uint_as_float(u1 & 0xFFFF0000u);
    asm("cvt.rn.bf16x2.f32 %0, %1, %2;" : "=r"(lo) : "f"(l1), "f"(l0));
}

__device__ __forceinline__ void mma16816(float* c,
    uint32_t a0, uint32_t a1, uint32_t a2, uint32_t a3, uint32_t b0, uint32_t b1)
{
    asm("mma.sync.aligned.m16n8k16.row.col.f32.bf16.bf16.f32 "
        "{%0,%1,%2,%3}, {%4,%5,%6,%7}, {%8,%9}, {%0,%1,%2,%3};"
        : "+f"(c[0]), "+f"(c[1]), "+f"(c[2]), "+f"(c[3])
        : "r"(a0), "r"(a1), "r"(a2), "r"(a3), "r"(b0), "r"(b1));
}

__device__ __forceinline__ void ldsm4(uint32_t* r, uint32_t saddr) {
    asm volatile("ldmatrix.sync.aligned.m8n8.x4.shared.b16 {%0,%1,%2,%3}, [%4];"
                 : "=r"(r[0]), "=r"(r[1]), "=r"(r[2]), "=r"(r[3]) : "r"(saddr));
}

// out[n,c] = relu( bias[c] + [t|X][n,:] @ W[:,c] ), K=640, M=128/block, 8 warps.
template<bool LAYER2>
__global__ __launch_bounds__(256) void gemm_mma_kernel(
    const float* __restrict__ Xext,
    const float* __restrict__ bias,
    float* __restrict__ Hext)
{
    // A chunk staged as bf16 hi/lo: 128 rows x 64 k = 128B/row, XOR-swizzled 16B units
    __shared__ __align__(128) uint32_t sAhi[128 * 32];
    __shared__ __align__(128) uint32_t sAlo[128 * 32];

    const float* X = LAYER2 ? g_x2 : Xext;
    float* H = LAYER2 ? Hext : g_x2;
    const uint4* wfrag = g_wfrag[LAYER2 ? 1 : 0];

    const int tid = threadIdx.x;
    const int w = tid >> 5, l = tid & 31;
    const int g = l >> 2, t2 = (l & 3) * 2;
    const int mbase = blockIdx.x * MTILE;
    const int R = w * 16;

    // ldmatrix source address (constant across chunks except unit parity)
    const int lm_row = R + ((l >> 3) & 1) * 8 + (l & 7);
    const int lm_uhalf = l >> 4;            // 0: k0-7, 1: k8-15
    const uint32_t sAhi_base = (uint32_t)__cvta_generic_to_shared(sAhi);
    const uint32_t sAlo_base = (uint32_t)__cvta_generic_to_shared(sAlo);

    float acc[8][4] = {};

    for (int s = 0; s < 10; s++) {
        __syncthreads();   // previous chunk fully consumed
        // ---- stage A chunk: coalesced float4 loads, split to bf16 hi/lo ----
        #pragma unroll
        for (int i = 0; i < 8; i++) {
            int lin = i * 256 + tid;
            int row = lin >> 4, c4 = lin & 15;
            int node = mbase + row;
            float4 v = make_float4(0.f, 0.f, 0.f, 0.f);
            if (node < N_NODES) {
                const float* src = (s < 9)
                    ? (g_t + (size_t)node * TCOLS + s * 64 + c4 * 4)
                    : (X + (size_t)node * CH + c4 * 4);
                v = *(const float4*)src;
            }
            uint32_t h0, l0, h1, l1;
            split2(v.x, v.y, h0, l0);
            split2(v.z, v.w, h1, l1);
            int off = row * 32 + ((((c4 >> 1) ^ (row & 7)) << 2) | ((c4 & 1) << 1));
            sAhi[off] = h0; sAhi[off + 1] = h1;
            sAlo[off] = l0; sAlo[off + 1] = l1;
        }
        __syncthreads();

        // ---- 4 K16 steps ----
        #pragma unroll
        for (int q = 0; q < 4; q++) {
            int unit = q * 2 + lm_uhalf;
            uint32_t soff = (uint32_t)(lm_row * 128 + ((unit ^ (lm_row & 7)) << 4));
            uint32_t ah[4], al[4];
            ldsm4(ah, sAhi_base + soff);
            ldsm4(al, sAlo_base + soff);

            const uint4* wp = wfrag + ((s * 4 + q) * 8) * 32 + l;
            #pragma unroll
            for (int nt = 0; nt < 8; nt++) {
                uint4 bf = __ldg(wp + nt * 32);
                mma16816(acc[nt], ah[0], ah[1], ah[2], ah[3], bf.x, bf.y);
                mma16816(acc[nt], ah[0], ah[1], ah[2], ah[3], bf.z, bf.w);
                mma16816(acc[nt], al[0], al[1], al[2], al[3], bf.x, bf.y);
            }
        }
    }

    // ---- epilogue: bias + relu; acc[nt] rows R+g / R+g+8, cols nt*8+t2 ----
    const int r0 = mbase + R + g, r1 = r0 + 8;
    #pragma unroll
    for (int nt = 0; nt < 8; nt++) {
        const int c = nt * 8 + t2;
        float b0 = __ldg(&bias[c]), b1 = __ldg(&bias[c + 1]);
        if (r0 < N_NODES) {
            float2 o = make_float2(fmaxf(acc[nt][0] + b0, 0.f),
                                   fmaxf(acc[nt][1] + b1, 0.f));
            *(float2*)&H[(size_t)r0 * CH + c] = o;
        }
        if (r1 < N_NODES) {
            float2 o = make_float2(fmaxf(acc[nt][2] + b0, 0.f),
                                   fmaxf(acc[nt][3] + b1, 0.f));
            *(float2*)&H[(size_t)r1 * CH + c] = o;
        }
    }
}

// ---------------------------------------------------------------------------
extern "C" void kernel_launch(void* const* d_in, const int* in_sizes, int n_in,
                              void* d_out, int out_size) {
    const float* x      = (const float*)d_in[0];
    const int* ei32     = (const int*)d_in[1];
    const float* pseudo = (const float*)d_in[2];
    const float* W1     = (const float*)d_in[3];
    const float* root1  = (const float*)d_in[4];
    const float* b1     = (const float*)d_in[5];
    const float* W2     = (const float*)d_in[6];
    const float* root2  = (const float*)d_in[7];
    const float* b2     = (const float*)d_in[8];
    float* out          = (float*)d_out;

    // ---- CSR build + weight-fragment prep (shared by both layers) ----
    detect_kernel<<<1, 32>>>(ei32);
    zero_kernel<<<(N_NODES + 255) / 256, 256>>>();
    convert_hist_kernel<<<(2 * N_EDGES + 255) / 256, 256>>>(ei32);
    scan1_kernel<<<NSCAN_BLOCKS, SCAN_B>>>();
    scan2_kernel<<<1, 1>>>();
    scan3_kernel<<<(N_NODES + 255) / 256, 256>>>();
    scatter_kernel<<<(N_EDGES + 255) / 256, 256>>>(pseudo);
    wprep_kernel<<<(NFRAG + 255) / 256, 256>>>(0, W1, root1);
    wprep_kernel<<<(NFRAG + 255) / 256, 256>>>(1, W2, root2);

    const int agg_grid = (N_NODES + 7) / 8;

    // ---- layer 1 ----
    agg_kernel<false><<<agg_grid, 256>>>(x);
    gemm_mma_kernel<false><<<GEMM_GRID, 256>>>(x, b1, nullptr);

    // ---- layer 2 ----
    agg_kernel<true><<<agg_grid, 256>>>(nullptr);
    gemm_mma_kernel<true><<<GEMM_GRID, 256>>>(nullptr, b2, out);
}

// round 10
// speedup vs baseline: 1.4197x; 1.0129x over previous
#include <cuda_runtime.h>
#include <cuda_bf16.h>
#include <cstdint>

#define N_NODES 100000
#define N_EDGES 1600000
#define CH 64
#define TCOLS 576               // 9 * 64
#define KDIM 640                // 576 + 64
#define SCAN_B 1024
#define NSCAN_BLOCKS ((N_NODES + SCAN_B - 1) / SCAN_B)   // 98
#define NKC 40                  // K16 steps
#define NFRAG (NKC * 8 * 32)    // 10240 uint4 per layer
#define FM 32                   // nodes per fused block
#define FGRID (N_NODES / FM)    // 3125 (exact)
#define ROWU 80                 // 16B units per smem row (640 bf16)
#define ROWB (ROWU * 16)        // 1280 bytes
#define TILE_BYTES (FM * ROWB)  // 40960 per hi/lo
#define FSMEM (2 * TILE_BYTES)  // 81920

struct __align__(16) EdgeRec {   // 64 B
    int src; int pad0; int pad1; int pad2;
    float b[9];
    float pad3; float pad4; float pad5;
};

// ------------------------- device scratch (no allocs) -----------------------
__device__ int     g_idx[2 * N_EDGES];
__device__ int     g_is64;
__device__ int     g_cnt[N_NODES];
__device__ int     g_cur[N_NODES];
__device__ int     g_row[N_NODES + 1];
__device__ int     g_bsum[NSCAN_BLOCKS];
__device__ int     g_boff[NSCAN_BLOCKS];
__device__ EdgeRec g_edges[N_EDGES];
__device__ float   g_x2[(size_t)N_NODES * CH];
// Fragment-ready split-bf16 weights: [layer][kc][nt][lane] = {bh0,bh1,bl0,bl1}
__device__ uint4   g_wfrag[2][NFRAG];

// --------------------------- CSR build --------------------------------------
__global__ void detect_kernel(const int* __restrict__ ei32) {
    int ok = 1;
    for (int i = threadIdx.x * 2 + 1; i < 512; i += 64)
        if (ei32[i] != 0) ok = 0;
    ok = __all_sync(0xffffffffu, ok) ? 1 : 0;
    if (threadIdx.x == 0) g_is64 = ok;
}

__global__ __launch_bounds__(256) void zero_kernel() {
    int i = blockIdx.x * 256 + threadIdx.x;
    if (i < N_NODES) { g_cnt[i] = 0; g_cur[i] = 0; }
}

__global__ __launch_bounds__(256) void convert_hist_kernel(const int* __restrict__ ei32) {
    int j = blockIdx.x * 256 + threadIdx.x;
    if (j >= 2 * N_EDGES) return;
    int is64 = g_is64;
    int v = is64 ? ei32[2 * j] : ei32[j];
    v = ((unsigned)v < (unsigned)N_NODES) ? v : 0;
    g_idx[j] = v;
    if (j >= N_EDGES) atomicAdd(&g_cnt[v], 1);
}

__global__ __launch_bounds__(SCAN_B) void scan1_kernel() {
    __shared__ int s[SCAN_B];
    int t = threadIdx.x;
    int i = blockIdx.x * SCAN_B + t;
    int v = (i < N_NODES) ? g_cnt[i] : 0;
    s[t] = v;
    __syncthreads();
    for (int off = 1; off < SCAN_B; off <<= 1) {
        int tmp = (t >= off) ? s[t - off] : 0;
        __syncthreads();
        s[t] += tmp;
        __syncthreads();
    }
    if (i < N_NODES) g_row[i] = s[t] - v;
    if (t == SCAN_B - 1) g_bsum[blockIdx.x] = s[t];
}

__global__ void scan2_kernel() {
    int run = 0;
    for (int b = 0; b < NSCAN_BLOCKS; b++) { g_boff[b] = run; run += g_bsum[b]; }
    g_row[N_NODES] = N_EDGES;
}

__global__ __launch_bounds__(256) void scan3_kernel() {
    int i = blockIdx.x * 256 + threadIdx.x;
    if (i < N_NODES) g_row[i] += g_boff[i >> 10];
}

__global__ __launch_bounds__(256) void scatter_kernel(const float* __restrict__ pseudo) {
    int e = blockIdx.x * 256 + threadIdx.x;
    if (e >= N_EDGES) return;
    int src = g_idx[e];
    int dst = g_idx[N_EDGES + e];
    float2 p = ((const float2*)pseudo)[e];
    float u = p.x, v = p.y;
    float bu0 = 0.5f * u * u - u + 0.5f, bu1 = -u * u + u + 0.5f, bu2 = 0.5f * u * u;
    float bv0 = 0.5f * v * v - v + 0.5f, bv1 = -v * v + v + 0.5f, bv2 = 0.5f * v * v;

    int pos = g_row[dst] + atomicAdd(&g_cur[dst], 1);
    float4* q = (float4*)&g_edges[pos];
    int4 s4 = make_int4(src, 0, 0, 0);
    q[0] = *(float4*)&s4;
    q[1] = make_float4(bu0 * bv0, bu0 * bv1, bu0 * bv2, bu1 * bv0);
    q[2] = make_float4(bu1 * bv1, bu1 * bv2, bu2 * bv0, bu2 * bv1);
    q[3] = make_float4(bu2 * bv2, 0.f, 0.f, 0.f);
}

// ------------------- Weight prep: fragment-ready table -----------------------
__device__ __forceinline__ uint32_t packbf2(float a, float b) {
    __nv_bfloat162 h;
    h.x = __float2bfloat16(a);
    h.y = __float2bfloat16(b);
    return *(uint32_t*)&h;
}

__global__ __launch_bounds__(256) void wprep_kernel(
    int layer, const float* __restrict__ W9, const float* __restrict__ root)
{
    int idx = blockIdx.x * 256 + threadIdx.x;
    if (idx >= NFRAG) return;
    int l  = idx & 31;
    int nt = (idx >> 5) & 7;
    int kc = idx >> 8;
    int g = l >> 2, t2 = (l & 3) * 2;
    int n = nt * 8 + g;
    int k0 = kc * 16 + t2;

    float w[4];   // k0, k0+1, k0+8, k0+9
    #pragma unroll
    for (int j = 0; j < 4; j++) {
        int kk = k0 + (j & 1) + (j >> 1) * 8;
        w[j] = (kk < TCOLS) ? W9[kk * 64 + n] : root[(kk - TCOLS) * 64 + n];
    }
    uint32_t bh0 = packbf2(w[0], w[1]);
    uint32_t bh1 = packbf2(w[2], w[3]);
    __nv_bfloat162* h0 = (__nv_bfloat162*)&bh0;
    __nv_bfloat162* h1 = (__nv_bfloat162*)&bh1;
    uint32_t bl0 = packbf2(w[0] - __bfloat162float(h0->x), w[1] - __bfloat162float(h0->y));
    uint32_t bl1 = packbf2(w[2] - __bfloat162float(h1->x), w[3] - __bfloat162float(h1->y));
    g_wfrag[layer][idx] = make_uint4(bh0, bh1, bl0, bl1);
}

// ------------------------------ helpers -------------------------------------
// hi = mantissa truncation of (x,y) packed bf16x2; lo = rn residual.
__device__ __forceinline__ void split2(float x, float y, uint32_t& hi, uint32_t& lo) {
    uint32_t u0 = __float_as_uint(x), u1 = __float_as_uint(y);
    asm("prmt.b32 %0, %1, %2, 0x7632;" : "=r"(hi) : "r"(u0), "r"(u1));
    float l0 = x - __uint_as_float(u0 & 0xFFFF0000u);
    float l1 = y - __uint_as_float(u1 & 0xFFFF0000u);
    asm("cvt.rn.bf16x2.f32 %0, %1, %2;" : "=r"(lo) : "f"(l1), "f"(l0));
}

__device__ __forceinline__ void mma16816(float* c,
    uint32_t a0, uint32_t a1, uint32_t a2, uint32_t a3, uint32_t b0, uint32_t b1)
{
    asm("mma.sync.aligned.m16n8k16.row.col.f32.bf16.bf16.f32 "
        "{%0,%1,%2,%3}, {%4,%5,%6,%7}, {%8,%9}, {%0,%1,%2,%3};"
        : "+f"(c[0]), "+f"(c[1]), "+f"(c[2]), "+f"(c[3])
        : "r"(a0), "r"(a1), "r"(a2), "r"(a3), "r"(b0), "r"(b1));
}

__device__ __forceinline__ void ldsm4(uint32_t* r, uint32_t saddr) {
    asm volatile("ldmatrix.sync.aligned.m8n8.x4.shared.b16 {%0,%1,%2,%3}, [%4];"
                 : "=r"(r[0]), "=r"(r[1]), "=r"(r[2]), "=r"(r[3]) : "r"(saddr));
}

// ---------------------------------------------------------------------------
// Fused layer kernel: per block of 32 dst nodes,
//   phase 1: stage X rows (k=576..639) into smem hi/lo
//   phase 2: CSR aggregation -> smem t tile (k=0..575) hi/lo
//   phase 3: split-bf16 mma GEMM from smem, bias+relu -> H
// smem rows: 640 bf16 = 80 x 16B units, XOR-swizzled (unit ^ (row&7)).
// ---------------------------------------------------------------------------
template<bool LAYER2>
__global__ __launch_bounds__(256) void fused_layer_kernel(
    const float* __restrict__ Xext,
    const float* __restrict__ bias,
    float* __restrict__ Hext)
{
    extern __shared__ __align__(128) char smem[];
    char* sHi = smem;
    char* sLo = smem + TILE_BYTES;

    const float* X = LAYER2 ? g_x2 : Xext;
    float* H = LAYER2 ? Hext : g_x2;
    const uint4* wfrag = g_wfrag[LAYER2 ? 1 : 0];

    const int tid = threadIdx.x;
    const int w = tid >> 5, l = tid & 31;
    const int g = l >> 2, t2 = (l & 3) * 2;
    const int mbase = blockIdx.x * FM;

    // ---- phase 1: X rows -> cols 576..639 ----
    {
        int r = tid >> 3, cg = tid & 7;          // r 0..31, cg 0..7 (8 cols each)
        const float* xp = X + (size_t)(mbase + r) * CH + cg * 8;
        float4 v0 = *(const float4*)xp;
        float4 v1 = *(const float4*)(xp + 4);
        uint32_t h0, l0, h1, l1, h2, l2, h3, l3;
        split2(v0.x, v0.y, h0, l0);
        split2(v0.z, v0.w, h1, l1);
        split2(v1.x, v1.y, h2, l2);
        split2(v1.z, v1.w, h3, l3);
        int phys = (72 + cg) ^ (r & 7);
        int off = r * ROWB + phys * 16;
        *(uint4*)(sHi + off) = make_uint4(h0, h1, h2, h3);
        *(uint4*)(sLo + off) = make_uint4(l0, l1, l2, l3);
    }

    // ---- phase 2: aggregation, warp w handles nodes mbase + w*4 .. +3 ----
    #pragma unroll
    for (int i = 0; i < 4; i++) {
        const int r = w * 4 + i;                 // local row
        const int node = mbase + r;
        int beg = g_row[node], end = g_row[node + 1];
        float acc[9][2] = {};

        #pragma unroll 4
        for (int e = beg; e < end; e++) {
            const EdgeRec* rec = &g_edges[e];
            int src = __ldg(&rec->src);
            float4 b03 = __ldg((const float4*)&rec->b[0]);
            float4 b47 = __ldg((const float4*)&rec->b[4]);
            float  b8  = __ldg(&rec->b[8]);
            float2 xv  = __ldg((const float2*)&X[(size_t)src * CH + 2 * l]);
            acc[0][0] += b03.x * xv.x; acc[0][1] += b03.x * xv.y;
            acc[1][0] += b03.y * xv.x; acc[1][1] += b03.y * xv.y;
            acc[2][0] += b03.z * xv.x; acc[2][1] += b03.z * xv.y;
            acc[3][0] += b03.w * xv.x; acc[3][1] += b03.w * xv.y;
            acc[4][0] += b47.x * xv.x; acc[4][1] += b47.x * xv.y;
            acc[5][0] += b47.y * xv.x; acc[5][1] += b47.y * xv.y;
            acc[6][0] += b47.z * xv.x; acc[6][1] += b47.z * xv.y;
            acc[7][0] += b47.w * xv.x; acc[7][1] += b47.w * xv.y;
            acc[8][0] += b8    * xv.x; acc[8][1] += b8    * xv.y;
        }

        // write t[r, k*64 + 2l .. +1] as hi/lo bf16x2 (4B per tap)
        #pragma unroll
        for (int k = 0; k < 9; k++) {
            uint32_t hi, lo;
            split2(acc[k][0], acc[k][1], hi, lo);
            int phys = (8 * k + (l >> 2)) ^ (r & 7);
            int off = r * ROWB + phys * 16 + (l & 3) * 4;
            *(uint32_t*)(sHi + off) = hi;
            *(uint32_t*)(sLo + off) = lo;
        }
    }
    __syncthreads();

    // ---- phase 3: mma. warp: m-half mh = w&1, n-quarter nq = w>>1 ----
    const int mh = w & 1, nq = w >> 1;
    const int lm_row = mh * 16 + ((l >> 3) & 1) * 8 + (l & 7);
    const int lm_uh = l >> 4;
    const uint32_t sHiB = (uint32_t)__cvta_generic_to_shared(sHi);
    const uint32_t sLoB = (uint32_t)__cvta_generic_to_shared(sLo);

    float acc0[4] = {}, acc1[4] = {};
    #pragma unroll 4
    for (int kc = 0; kc < NKC; kc++) {
        int unit = 2 * kc + lm_uh;
        uint32_t soff = (uint32_t)(lm_row * ROWB + ((unit ^ (lm_row & 7)) << 4));
        uint32_t ah[4], al[4];
        ldsm4(ah, sHiB + soff);
        ldsm4(al, sLoB + soff);

        const uint4* wp = wfrag + (kc * 8 + nq * 2) * 32 + l;
        uint4 bf0 = __ldg(wp);
        uint4 bf1 = __ldg(wp + 32);
        mma16816(acc0, ah[0], ah[1], ah[2], ah[3], bf0.x, bf0.y);
        mma16816(acc0, ah[0], ah[1], ah[2], ah[3], bf0.z, bf0.w);
        mma16816(acc0, al[0], al[1], al[2], al[3], bf0.x, bf0.y);
        mma16816(acc1, ah[0], ah[1], ah[2], ah[3], bf1.x, bf1.y);
        mma16816(acc1, ah[0], ah[1], ah[2], ah[3], bf1.z, bf1.w);
        mma16816(acc1, al[0], al[1], al[2], al[3], bf1.x, bf1.y);
    }

    // ---- epilogue: bias + relu ----
    const int r0 = mbase + mh * 16 + g, r1 = r0 + 8;
    #pragma unroll
    for (int j = 0; j < 2; j++) {
        float* a = j ? acc1 : acc0;
        const int c = (nq * 2 + j) * 8 + t2;
        float b0 = __ldg(&bias[c]), b1 = __ldg(&bias[c + 1]);
        *(float2*)&H[(size_t)r0 * CH + c] =
            make_float2(fmaxf(a[0] + b0, 0.f), fmaxf(a[1] + b1, 0.f));
        *(float2*)&H[(size_t)r1 * CH + c] =
            make_float2(fmaxf(a[2] + b0, 0.f), fmaxf(a[3] + b1, 0.f));
    }
}

// ---------------------------------------------------------------------------
extern "C" void kernel_launch(void* const* d_in, const int* in_sizes, int n_in,
                              void* d_out, int out_size) {
    const float* x      = (const float*)d_in[0];
    const int* ei32     = (const int*)d_in[1];
    const float* pseudo = (const float*)d_in[2];
    const float* W1     = (const float*)d_in[3];
    const float* root1  = (const float*)d_in[4];
    const float* b1     = (const float*)d_in[5];
    const float* W2     = (const float*)d_in[6];
    const float* root2  = (const float*)d_in[7];
    const float* b2     = (const float*)d_in[8];
    float* out          = (float*)d_out;

    cudaFuncSetAttribute(fused_layer_kernel<false>,
                         cudaFuncAttributeMaxDynamicSharedMemorySize, FSMEM);
    cudaFuncSetAttribute(fused_layer_kernel<true>,
                         cudaFuncAttributeMaxDynamicSharedMemorySize, FSMEM);

    // ---- CSR build + weight-fragment prep (shared by both layers) ----
    detect_kernel<<<1, 32>>>(ei32);
    zero_kernel<<<(N_NODES + 255) / 256, 256>>>();
    convert_hist_kernel<<<(2 * N_EDGES + 255) / 256, 256>>>(ei32);
    scan1_kernel<<<NSCAN_BLOCKS, SCAN_B>>>();
    scan2_kernel<<<1, 1>>>();
    scan3_kernel<<<(N_NODES + 255) / 256, 256>>>();
    scatter_kernel<<<(N_EDGES + 255) / 256, 256>>>(pseudo);
    wprep_kernel<<<(NFRAG + 255) / 256, 256>>>(0, W1, root1);
    wprep_kernel<<<(NFRAG + 255) / 256, 256>>>(1, W2, root2);

    // ---- fused layers ----
    fused_layer_kernel<false><<<FGRID, 256, FSMEM>>>(x, b1, nullptr);
    fused_layer_kernel<true><<<FGRID, 256, FSMEM>>>(nullptr, b2, out);
}

// round 11
// speedup vs baseline: 1.4379x; 1.0128x over previous
#include <cuda_runtime.h>
#include <cuda_bf16.h>
#include <cstdint>

#define N_NODES 100000
#define N_EDGES 1600000
#define CH 64
#define TCOLS 576               // 9 * 64
#define KDIM 640                // 576 + 64
#define SCAN_B 1024
#define NSCAN_BLOCKS ((N_NODES + SCAN_B - 1) / SCAN_B)   // 98
#define NKC 40                  // K16 steps
#define NFRAG (NKC * 8 * 32)    // 10240 uint4 per layer
#define FM 32                   // nodes per fused block
#define FGRID (N_NODES / FM)    // 3125 (exact)
#define ROWU 80                 // 16B units per smem row (640 bf16)
#define ROWB (ROWU * 16)        // 1280 bytes
#define TILE_BYTES (FM * ROWB)  // 40960 per hi/lo
#define FSMEM (2 * TILE_BYTES)  // 81920
#define CONV_BLOCKS ((2 * N_EDGES + 255) / 256)   // 12500
#define WPREP_BLOCKS ((2 * NFRAG + 255) / 256)    // 80

struct __align__(16) EdgeRec {   // 64 B
    int src; int pad0; int pad1; int pad2;
    float b[9];
    float pad3; float pad4; float pad5;
};

// ------------------------- device scratch (no allocs) -----------------------
__device__ int     g_idx[2 * N_EDGES];
__device__ int     g_cnt[N_NODES];
__device__ int     g_cur[N_NODES];
__device__ int     g_row[N_NODES + 1];
__device__ int     g_bsum[NSCAN_BLOCKS];
__device__ int     g_ready;        // scan rendezvous; reset by scatter for next call
__device__ EdgeRec g_edges[N_EDGES];
__device__ float   g_x2[(size_t)N_NODES * CH];
// Fragment-ready split-bf16 weights: [layer][kc][nt][lane] = {bh0,bh1,bl0,bl1}
__device__ uint4   g_wfrag[2][NFRAG];

// ------------------------------ helpers -------------------------------------
__device__ __forceinline__ uint32_t packbf2(float a, float b) {
    __nv_bfloat162 h;
    h.x = __float2bfloat16(a);
    h.y = __float2bfloat16(b);
    return *(uint32_t*)&h;
}

// hi = mantissa truncation of (x,y) packed bf16x2; lo = rn residual.
__device__ __forceinline__ void split2(float x, float y, uint32_t& hi, uint32_t& lo) {
    uint32_t u0 = __float_as_uint(x), u1 = __float_as_uint(y);
    asm("prmt.b32 %0, %1, %2, 0x7632;" : "=r"(hi) : "r"(u0), "r"(u1));
    float l0 = x - __uint_as_float(u0 & 0xFFFF0000u);
    float l1 = y - __uint_as_float(u1 & 0xFFFF0000u);
    asm("cvt.rn.bf16x2.f32 %0, %1, %2;" : "=r"(lo) : "f"(l1), "f"(l0));
}

__device__ __forceinline__ void mma16816(float* c,
    uint32_t a0, uint32_t a1, uint32_t a2, uint32_t a3, uint32_t b0, uint32_t b1)
{
    asm("mma.sync.aligned.m16n8k16.row.col.f32.bf16.bf16.f32 "
        "{%0,%1,%2,%3}, {%4,%5,%6,%7}, {%8,%9}, {%0,%1,%2,%3};"
        : "+f"(c[0]), "+f"(c[1]), "+f"(c[2]), "+f"(c[3])
        : "r"(a0), "r"(a1), "r"(a2), "r"(a3), "r"(b0), "r"(b1));
}

__device__ __forceinline__ void ldsm4(uint32_t* r, uint32_t saddr) {
    asm volatile("ldmatrix.sync.aligned.m8n8.x4.shared.b16 {%0,%1,%2,%3}, [%4];"
                 : "=r"(r[0]), "=r"(r[1]), "=r"(r[2]), "=r"(r[3]) : "r"(saddr));
}

// ---------------------------------------------------------------------------
// Launch 0: convert+histogram (with per-block inline dtype detection) and,
// in the trailing 80 blocks, weight-fragment prep for both layers.
// Needs g_cnt == 0 on entry (module init / restored by scan_kernel).
// ---------------------------------------------------------------------------
__global__ __launch_bounds__(256) void convert_hist_wprep_kernel(
    const int* __restrict__ ei32,
    const float* __restrict__ W1, const float* __restrict__ root1,
    const float* __restrict__ W2, const float* __restrict__ root2)
{
    const int b = blockIdx.x;
    if (b < CONV_BLOCKS) {
        // inline dtype detection: int64-with-small-values => odd words all zero
        __shared__ int s_is64;
        if (threadIdx.x < 32) {
            int ok = 1;
            for (int i = threadIdx.x * 2 + 1; i < 512; i += 64)
                if (ei32[i] != 0) ok = 0;
            ok = __all_sync(0xffffffffu, ok) ? 1 : 0;
            if (threadIdx.x == 0) s_is64 = ok;
        }
        __syncthreads();
        const int is64 = s_is64;

        int j = b * 256 + threadIdx.x;
        if (j < 2 * N_EDGES) {
            int v = is64 ? ei32[2 * j] : ei32[j];
            v = ((unsigned)v < (unsigned)N_NODES) ? v : 0;
            g_idx[j] = v;
            if (j >= N_EDGES) atomicAdd(&g_cnt[v], 1);
        }
    } else {
        int idx = (b - CONV_BLOCKS) * 256 + threadIdx.x;   // 0 .. 2*NFRAG-1
        if (idx >= 2 * NFRAG) return;
        const int layer = idx >= NFRAG;
        const int fi = layer ? idx - NFRAG : idx;
        const float* W9   = layer ? W2 : W1;
        const float* root = layer ? root2 : root1;

        int l  = fi & 31;
        int nt = (fi >> 5) & 7;
        int kc = fi >> 8;
        int g = l >> 2, t2 = (l & 3) * 2;
        int n = nt * 8 + g;
        int k0 = kc * 16 + t2;

        float w[4];   // k0, k0+1, k0+8, k0+9
        #pragma unroll
        for (int j2 = 0; j2 < 4; j2++) {
            int kk = k0 + (j2 & 1) + (j2 >> 1) * 8;
            w[j2] = (kk < TCOLS) ? W9[kk * 64 + n] : root[(kk - TCOLS) * 64 + n];
        }
        uint32_t bh0 = packbf2(w[0], w[1]);
        uint32_t bh1 = packbf2(w[2], w[3]);
        __nv_bfloat162* h0 = (__nv_bfloat162*)&bh0;
        __nv_bfloat162* h1 = (__nv_bfloat162*)&bh1;
        uint32_t bl0 = packbf2(w[0] - __bfloat162float(h0->x), w[1] - __bfloat162float(h0->y));
        uint32_t bl1 = packbf2(w[2] - __bfloat162float(h1->x), w[3] - __bfloat162float(h1->y));
        g_wfrag[layer][fi] = make_uint4(bh0, bh1, bl0, bl1);
    }
}

// ---------------------------------------------------------------------------
// Launch 1: single-pass exclusive scan (98 co-resident blocks rendezvous via
// g_ready), then zero g_cnt/g_cur for the next call (self-restoring state).
// ---------------------------------------------------------------------------
__global__ __launch_bounds__(SCAN_B) void scan_kernel() {
    __shared__ int s[SCAN_B];
    __shared__ int s_prev;
    const int t = threadIdx.x, b = blockIdx.x;
    const int i = b * SCAN_B + t;
    int v = (i < N_NODES) ? g_cnt[i] : 0;
    s[t] = v;
    __syncthreads();
    for (int off = 1; off < SCAN_B; off <<= 1) {
        int tmp = (t >= off) ? s[t - off] : 0;
        __syncthreads();
        s[t] += tmp;
        __syncthreads();
    }
    if (t == SCAN_B - 1) {
        g_bsum[b] = s[t];
        __threadfence();
        atomicAdd(&g_ready, 1);
    }
    if (t == 0) {
        while (*(volatile int*)&g_ready < NSCAN_BLOCKS) { }
        __threadfence();
        int p = 0;
        for (int q = 0; q < b; q++) p += __ldcg(&g_bsum[q]);
        s_prev = p;
    }
    __syncthreads();
    if (i < N_NODES) {
        g_row[i] = s_prev + s[t] - v;   // exclusive prefix
        g_cnt[i] = 0;                   // restore for next call
        g_cur[i] = 0;
    }
    if (b == 0 && t == 0) g_row[N_NODES] = N_EDGES;
}

// ---------------------------------------------------------------------------
// Launch 2: scatter edges into dst-sorted order + precompute basis weights.
// Also resets g_ready for the next call's scan.
// ---------------------------------------------------------------------------
__global__ __launch_bounds__(256) void scatter_kernel(const float* __restrict__ pseudo) {
    if (blockIdx.x == 0 && threadIdx.x == 0) g_ready = 0;
    int e = blockIdx.x * 256 + threadIdx.x;
    if (e >= N_EDGES) return;
    int src = g_idx[e];
    int dst = g_idx[N_EDGES + e];
    float2 p = ((const float2*)pseudo)[e];
    float u = p.x, v = p.y;
    float bu0 = 0.5f * u * u - u + 0.5f, bu1 = -u * u + u + 0.5f, bu2 = 0.5f * u * u;
    float bv0 = 0.5f * v * v - v + 0.5f, bv1 = -v * v + v + 0.5f, bv2 = 0.5f * v * v;

    int pos = g_row[dst] + atomicAdd(&g_cur[dst], 1);
    float4* q = (float4*)&g_edges[pos];
    int4 s4 = make_int4(src, 0, 0, 0);
    q[0] = *(float4*)&s4;
    q[1] = make_float4(bu0 * bv0, bu0 * bv1, bu0 * bv2, bu1 * bv0);
    q[2] = make_float4(bu1 * bv1, bu1 * bv2, bu2 * bv0, bu2 * bv1);
    q[3] = make_float4(bu2 * bv2, 0.f, 0.f, 0.f);
}

// ---------------------------------------------------------------------------
// Launches 3,4: fused layer (unchanged from R10).
//   phase 1: stage X rows (k=576..639) into smem hi/lo
//   phase 2: CSR aggregation -> smem t tile (k=0..575) hi/lo
//   phase 3: split-bf16 mma GEMM from smem, bias+relu -> H
// ---------------------------------------------------------------------------
template<bool LAYER2>
__global__ __launch_bounds__(256) void fused_layer_kernel(
    const float* __restrict__ Xext,
    const float* __restrict__ bias,
    float* __restrict__ Hext)
{
    extern __shared__ __align__(128) char smem[];
    char* sHi = smem;
    char* sLo = smem + TILE_BYTES;

    const float* X = LAYER2 ? g_x2 : Xext;
    float* H = LAYER2 ? Hext : g_x2;
    const uint4* wfrag = g_wfrag[LAYER2 ? 1 : 0];

    const int tid = threadIdx.x;
    const int w = tid >> 5, l = tid & 31;
    const int g = l >> 2, t2 = (l & 3) * 2;
    const int mbase = blockIdx.x * FM;

    // ---- phase 1: X rows -> cols 576..639 ----
    {
        int r = tid >> 3, cg = tid & 7;
        const float* xp = X + (size_t)(mbase + r) * CH + cg * 8;
        float4 v0 = *(const float4*)xp;
        float4 v1 = *(const float4*)(xp + 4);
        uint32_t h0, l0, h1, l1, h2, l2, h3, l3;
        split2(v0.x, v0.y, h0, l0);
        split2(v0.z, v0.w, h1, l1);
        split2(v1.x, v1.y, h2, l2);
        split2(v1.z, v1.w, h3, l3);
        int phys = (72 + cg) ^ (r & 7);
        int off = r * ROWB + phys * 16;
        *(uint4*)(sHi + off) = make_uint4(h0, h1, h2, h3);
        *(uint4*)(sLo + off) = make_uint4(l0, l1, l2, l3);
    }

    // ---- phase 2: aggregation, warp w handles nodes mbase + w*4 .. +3 ----
    #pragma unroll
    for (int i = 0; i < 4; i++) {
        const int r = w * 4 + i;
        const int node = mbase + r;
        int beg = g_row[node], end = g_row[node + 1];
        float acc[9][2] = {};

        #pragma unroll 4
        for (int e = beg; e < end; e++) {
            const EdgeRec* rec = &g_edges[e];
            int src = __ldg(&rec->src);
            float4 b03 = __ldg((const float4*)&rec->b[0]);
            float4 b47 = __ldg((const float4*)&rec->b[4]);
            float  b8  = __ldg(&rec->b[8]);
            float2 xv  = __ldg((const float2*)&X[(size_t)src * CH + 2 * l]);
            acc[0][0] += b03.x * xv.x; acc[0][1] += b03.x * xv.y;
            acc[1][0] += b03.y * xv.x; acc[1][1] += b03.y * xv.y;
            acc[2][0] += b03.z * xv.x; acc[2][1] += b03.z * xv.y;
            acc[3][0] += b03.w * xv.x; acc[3][1] += b03.w * xv.y;
            acc[4][0] += b47.x * xv.x; acc[4][1] += b47.x * xv.y;
            acc[5][0] += b47.y * xv.x; acc[5][1] += b47.y * xv.y;
            acc[6][0] += b47.z * xv.x; acc[6][1] += b47.z * xv.y;
            acc[7][0] += b47.w * xv.x; acc[7][1] += b47.w * xv.y;
            acc[8][0] += b8    * xv.x; acc[8][1] += b8    * xv.y;
        }

        #pragma unroll
        for (int k = 0; k < 9; k++) {
            uint32_t hi, lo;
            split2(acc[k][0], acc[k][1], hi, lo);
            int phys = (8 * k + (l >> 2)) ^ (r & 7);
            int off = r * ROWB + phys * 16 + (l & 3) * 4;
            *(uint32_t*)(sHi + off) = hi;
            *(uint32_t*)(sLo + off) = lo;
        }
    }
    __syncthreads();

    // ---- phase 3: mma. warp: m-half mh = w&1, n-quarter nq = w>>1 ----
    const int mh = w & 1, nq = w >> 1;
    const int lm_row = mh * 16 + ((l >> 3) & 1) * 8 + (l & 7);
    const int lm_uh = l >> 4;
    const uint32_t sHiB = (uint32_t)__cvta_generic_to_shared(sHi);
    const uint32_t sLoB = (uint32_t)__cvta_generic_to_shared(sLo);

    float acc0[4] = {}, acc1[4] = {};
    #pragma unroll 4
    for (int kc = 0; kc < NKC; kc++) {
        int unit = 2 * kc + lm_uh;
        uint32_t soff = (uint32_t)(lm_row * ROWB + ((unit ^ (lm_row & 7)) << 4));
        uint32_t ah[4], al[4];
        ldsm4(ah, sHiB + soff);
        ldsm4(al, sLoB + soff);

        const uint4* wp = wfrag + (kc * 8 + nq * 2) * 32 + l;
        uint4 bf0 = __ldg(wp);
        uint4 bf1 = __ldg(wp + 32);
        mma16816(acc0, ah[0], ah[1], ah[2], ah[3], bf0.x, bf0.y);
        mma16816(acc0, ah[0], ah[1], ah[2], ah[3], bf0.z, bf0.w);
        mma16816(acc0, al[0], al[1], al[2], al[3], bf0.x, bf0.y);
        mma16816(acc1, ah[0], ah[1], ah[2], ah[3], bf1.x, bf1.y);
        mma16816(acc1, ah[0], ah[1], ah[2], ah[3], bf1.z, bf1.w);
        mma16816(acc1, al[0], al[1], al[2], al[3], bf1.x, bf1.y);
    }

    // ---- epilogue: bias + relu ----
    const int r0 = mbase + mh * 16 + g, r1 = r0 + 8;
    #pragma unroll
    for (int j = 0; j < 2; j++) {
        float* a = j ? acc1 : acc0;
        const int c = (nq * 2 + j) * 8 + t2;
        float b0 = __ldg(&bias[c]), b1 = __ldg(&bias[c + 1]);
        *(float2*)&H[(size_t)r0 * CH + c] =
            make_float2(fmaxf(a[0] + b0, 0.f), fmaxf(a[1] + b1, 0.f));
        *(float2*)&H[(size_t)r1 * CH + c] =
            make_float2(fmaxf(a[2] + b0, 0.f), fmaxf(a[3] + b1, 0.f));
    }
}

// ---------------------------------------------------------------------------
extern "C" void kernel_launch(void* const* d_in, const int* in_sizes, int n_in,
                              void* d_out, int out_size) {
    const float* x      = (const float*)d_in[0];
    const int* ei32     = (const int*)d_in[1];
    const float* pseudo = (const float*)d_in[2];
    const float* W1     = (const float*)d_in[3];
    const float* root1  = (const float*)d_in[4];
    const float* b1     = (const float*)d_in[5];
    const float* W2     = (const float*)d_in[6];
    const float* root2  = (const float*)d_in[7];
    const float* b2     = (const float*)d_in[8];
    float* out          = (float*)d_out;

    cudaFuncSetAttribute(fused_layer_kernel<false>,
                         cudaFuncAttributeMaxDynamicSharedMemorySize, FSMEM);
    cudaFuncSetAttribute(fused_layer_kernel<true>,
                         cudaFuncAttributeMaxDynamicSharedMemorySize, FSMEM);

    // Launch 0: convert + histogram + weight prep
    convert_hist_wprep_kernel<<<CONV_BLOCKS + WPREP_BLOCKS, 256>>>(
        ei32, W1, root1, W2, root2);
    // Launch 1: single-pass scan (also restores g_cnt/g_cur to zero)
    scan_kernel<<<NSCAN_BLOCKS, SCAN_B>>>();
    // Launch 2: dst-sorted edge scatter + basis precompute
    scatter_kernel<<<(N_EDGES + 255) / 256, 256>>>(pseudo);
    // Launch 3 (profiled): fused layer 1
    fused_layer_kernel<false><<<FGRID, 256, FSMEM>>>(x, b1, nullptr);
    // Launch 4: fused layer 2
    fused_layer_kernel<true><<<FGRID, 256, FSMEM>>>(nullptr, b2, out);
}

// round 12
// speedup vs baseline: 1.9571x; 1.3611x over previous
#include <cuda_runtime.h>
#include <cuda_bf16.h>
#include <cstdint>

#define N_NODES 100000
#define N_EDGES 1600000
#define CH 64
#define TCOLS 576               // 9 * 64
#define KDIM 640                // 576 + 64
#define SCAN_B 1024
#define NSCAN_BLOCKS ((N_NODES + SCAN_B - 1) / SCAN_B)   // 98
#define NKC 40                  // K16 steps
#define NFRAG (NKC * 8 * 32)    // 10240 uint4 per layer
#define FM 16                   // nodes per fused block
#define FGRID (N_NODES / FM)    // 6250 (exact)
#define ROWU 80                 // 16B units per smem row (640 bf16)
#define ROWB (ROWU * 16)        // 1280 bytes
#define TILE_BYTES (FM * ROWB)  // 20480 per hi/lo
#define FSMEM (2 * TILE_BYTES)  // 40960
#define CONV_BLOCKS ((2 * N_EDGES + 255) / 256)   // 12500
#define WPREP_BLOCKS ((2 * NFRAG + 255) / 256)    // 80

struct __align__(16) EdgeRec {   // 64 B
    int src; int pad0; int pad1; int pad2;
    float b[9];
    float pad3; float pad4; float pad5;
};

// ------------------------- device scratch (no allocs) -----------------------
__device__ int     g_idx[2 * N_EDGES];
__device__ int     g_cnt[N_NODES];
__device__ int     g_cur[N_NODES];
__device__ int     g_row[N_NODES + 1];
__device__ int     g_bsum[NSCAN_BLOCKS];
__device__ int     g_ready;        // scan rendezvous; reset by scatter for next call
__device__ EdgeRec g_edges[N_EDGES];
__device__ float   g_x2[(size_t)N_NODES * CH];
// Fragment-ready split-bf16 weights: [layer][kc][nt][lane] = {bh0,bh1,bl0,bl1}
__device__ uint4   g_wfrag[2][NFRAG];

// ------------------------------ helpers -------------------------------------
__device__ __forceinline__ uint32_t packbf2(float a, float b) {
    __nv_bfloat162 h;
    h.x = __float2bfloat16(a);
    h.y = __float2bfloat16(b);
    return *(uint32_t*)&h;
}

// hi = mantissa truncation of (x,y) packed bf16x2; lo = rn residual.
__device__ __forceinline__ void split2(float x, float y, uint32_t& hi, uint32_t& lo) {
    uint32_t u0 = __float_as_uint(x), u1 = __float_as_uint(y);
    asm("prmt.b32 %0, %1, %2, 0x7632;" : "=r"(hi) : "r"(u0), "r"(u1));
    float l0 = x - __uint_as_float(u0 & 0xFFFF0000u);
    float l1 = y - __uint_as_float(u1 & 0xFFFF0000u);
    asm("cvt.rn.bf16x2.f32 %0, %1, %2;" : "=r"(lo) : "f"(l1), "f"(l0));
}

__device__ __forceinline__ void mma16816(float* c,
    uint32_t a0, uint32_t a1, uint32_t a2, uint32_t a3, uint32_t b0, uint32_t b1)
{
    asm("mma.sync.aligned.m16n8k16.row.col.f32.bf16.bf16.f32 "
        "{%0,%1,%2,%3}, {%4,%5,%6,%7}, {%8,%9}, {%0,%1,%2,%3};"
        : "+f"(c[0]), "+f"(c[1]), "+f"(c[2]), "+f"(c[3])
        : "r"(a0), "r"(a1), "r"(a2), "r"(a3), "r"(b0), "r"(b1));
}

__device__ __forceinline__ void ldsm4(uint32_t* r, uint32_t saddr) {
    asm volatile("ldmatrix.sync.aligned.m8n8.x4.shared.b16 {%0,%1,%2,%3}, [%4];"
                 : "=r"(r[0]), "=r"(r[1]), "=r"(r[2]), "=r"(r[3]) : "r"(saddr));
}

// ---------------------------------------------------------------------------
// Launch 0: convert+histogram (inline dtype detection) + weight-fragment prep.
// ---------------------------------------------------------------------------
__global__ __launch_bounds__(256) void convert_hist_wprep_kernel(
    const int* __restrict__ ei32,
    const float* __restrict__ W1, const float* __restrict__ root1,
    const float* __restrict__ W2, const float* __restrict__ root2)
{
    const int b = blockIdx.x;
    if (b < CONV_BLOCKS) {
        __shared__ int s_is64;
        if (threadIdx.x < 32) {
            int ok = 1;
            for (int i = threadIdx.x * 2 + 1; i < 512; i += 64)
                if (ei32[i] != 0) ok = 0;
            ok = __all_sync(0xffffffffu, ok) ? 1 : 0;
            if (threadIdx.x == 0) s_is64 = ok;
        }
        __syncthreads();
        const int is64 = s_is64;

        int j = b * 256 + threadIdx.x;
        if (j < 2 * N_EDGES) {
            int v = is64 ? ei32[2 * j] : ei32[j];
            v = ((unsigned)v < (unsigned)N_NODES) ? v : 0;
            g_idx[j] = v;
            if (j >= N_EDGES) atomicAdd(&g_cnt[v], 1);
        }
    } else {
        int idx = (b - CONV_BLOCKS) * 256 + threadIdx.x;
        if (idx >= 2 * NFRAG) return;
        const int layer = idx >= NFRAG;
        const int fi = layer ? idx - NFRAG : idx;
        const float* W9   = layer ? W2 : W1;
        const float* root = layer ? root2 : root1;

        int l  = fi & 31;
        int nt = (fi >> 5) & 7;
        int kc = fi >> 8;
        int g = l >> 2, t2 = (l & 3) * 2;
        int n = nt * 8 + g;
        int k0 = kc * 16 + t2;

        float w[4];   // k0, k0+1, k0+8, k0+9
        #pragma unroll
        for (int j2 = 0; j2 < 4; j2++) {
            int kk = k0 + (j2 & 1) + (j2 >> 1) * 8;
            w[j2] = (kk < TCOLS) ? W9[kk * 64 + n] : root[(kk - TCOLS) * 64 + n];
        }
        uint32_t bh0 = packbf2(w[0], w[1]);
        uint32_t bh1 = packbf2(w[2], w[3]);
        __nv_bfloat162* h0 = (__nv_bfloat162*)&bh0;
        __nv_bfloat162* h1 = (__nv_bfloat162*)&bh1;
        uint32_t bl0 = packbf2(w[0] - __bfloat162float(h0->x), w[1] - __bfloat162float(h0->y));
        uint32_t bl1 = packbf2(w[2] - __bfloat162float(h1->x), w[3] - __bfloat162float(h1->y));
        g_wfrag[layer][fi] = make_uint4(bh0, bh1, bl0, bl1);
    }
}

// ---------------------------------------------------------------------------
// Launch 1: single-pass exclusive scan; restores g_cnt/g_cur for next call.
// ---------------------------------------------------------------------------
__global__ __launch_bounds__(SCAN_B) void scan_kernel() {
    __shared__ int s[SCAN_B];
    __shared__ int s_prev;
    const int t = threadIdx.x, b = blockIdx.x;
    const int i = b * SCAN_B + t;
    int v = (i < N_NODES) ? g_cnt[i] : 0;
    s[t] = v;
    __syncthreads();
    for (int off = 1; off < SCAN_B; off <<= 1) {
        int tmp = (t >= off) ? s[t - off] : 0;
        __syncthreads();
        s[t] += tmp;
        __syncthreads();
    }
    if (t == SCAN_B - 1) {
        g_bsum[b] = s[t];
        __threadfence();
        atomicAdd(&g_ready, 1);
    }
    if (t == 0) {
        while (*(volatile int*)&g_ready < NSCAN_BLOCKS) { }
        __threadfence();
        int p = 0;
        for (int q = 0; q < b; q++) p += __ldcg(&g_bsum[q]);
        s_prev = p;
    }
    __syncthreads();
    if (i < N_NODES) {
        g_row[i] = s_prev + s[t] - v;
        g_cnt[i] = 0;
        g_cur[i] = 0;
    }
    if (b == 0 && t == 0) g_row[N_NODES] = N_EDGES;
}

// ---------------------------------------------------------------------------
// Launch 2: dst-sorted scatter + basis precompute; resets g_ready.
// ---------------------------------------------------------------------------
__global__ __launch_bounds__(256) void scatter_kernel(const float* __restrict__ pseudo) {
    if (blockIdx.x == 0 && threadIdx.x == 0) g_ready = 0;
    int e = blockIdx.x * 256 + threadIdx.x;
    if (e >= N_EDGES) return;
    int src = g_idx[e];
    int dst = g_idx[N_EDGES + e];
    float2 p = ((const float2*)pseudo)[e];
    float u = p.x, v = p.y;
    float bu0 = 0.5f * u * u - u + 0.5f, bu1 = -u * u + u + 0.5f, bu2 = 0.5f * u * u;
    float bv0 = 0.5f * v * v - v + 0.5f, bv1 = -v * v + v + 0.5f, bv2 = 0.5f * v * v;

    int pos = g_row[dst] + atomicAdd(&g_cur[dst], 1);
    float4* q = (float4*)&g_edges[pos];
    int4 s4 = make_int4(src, 0, 0, 0);
    q[0] = *(float4*)&s4;
    q[1] = make_float4(bu0 * bv0, bu0 * bv1, bu0 * bv2, bu1 * bv0);
    q[2] = make_float4(bu1 * bv1, bu1 * bv2, bu2 * bv0, bu2 * bv1);
    q[3] = make_float4(bu2 * bv2, 0.f, 0.f, 0.f);
}

// ---------------------------------------------------------------------------
// Launches 3,4: fused layer, FM=16 nodes/block (40KB smem -> ~4 CTAs/SM).
//   phase 1: stage X rows (k=576..639) into smem hi/lo
//   phase 2: CSR aggregation -> smem t tile (k=0..575), warp w: nodes w*2..+1
//   phase 3: warp w computes m16n8 output tile n-cols w*8..w*8+7
// ---------------------------------------------------------------------------
template<bool LAYER2>
__global__ __launch_bounds__(256) void fused_layer_kernel(
    const float* __restrict__ Xext,
    const float* __restrict__ bias,
    float* __restrict__ Hext)
{
    extern __shared__ __align__(128) char smem[];
    char* sHi = smem;
    char* sLo = smem + TILE_BYTES;

    const float* X = LAYER2 ? g_x2 : Xext;
    float* H = LAYER2 ? Hext : g_x2;
    const uint4* wfrag = g_wfrag[LAYER2 ? 1 : 0];

    const int tid = threadIdx.x;
    const int w = tid >> 5, l = tid & 31;
    const int g = l >> 2, t2 = (l & 3) * 2;
    const int mbase = blockIdx.x * FM;

    // ---- phase 1: X rows -> cols 576..639 (16 rows x 16 col-quads) ----
    {
        int r = tid >> 4, cg = tid & 15;         // r 0..15, cg 0..15 (4 cols each)
        const float* xp = X + (size_t)(mbase + r) * CH + cg * 4;
        float4 v0 = *(const float4*)xp;
        uint32_t h0, l0, h1, l1;
        split2(v0.x, v0.y, h0, l0);
        split2(v0.z, v0.w, h1, l1);
        int phys = (72 + (cg >> 1)) ^ (r & 7);
        int off = r * ROWB + phys * 16 + (cg & 1) * 8;
        *(uint2*)(sHi + off) = make_uint2(h0, h1);
        *(uint2*)(sLo + off) = make_uint2(l0, l1);
    }

    // ---- phase 2: aggregation, warp w handles nodes mbase + w*2 .. +1 ----
    #pragma unroll
    for (int i = 0; i < 2; i++) {
        const int r = w * 2 + i;
        const int node = mbase + r;
        int beg = g_row[node], end = g_row[node + 1];
        float acc[9][2] = {};

        #pragma unroll 4
        for (int e = beg; e < end; e++) {
            const EdgeRec* rec = &g_edges[e];
            int src = __ldg(&rec->src);
            float4 b03 = __ldg((const float4*)&rec->b[0]);
            float4 b47 = __ldg((const float4*)&rec->b[4]);
            float  b8  = __ldg(&rec->b[8]);
            float2 xv  = __ldg((const float2*)&X[(size_t)src * CH + 2 * l]);
            acc[0][0] += b03.x * xv.x; acc[0][1] += b03.x * xv.y;
            acc[1][0] += b03.y * xv.x; acc[1][1] += b03.y * xv.y;
            acc[2][0] += b03.z * xv.x; acc[2][1] += b03.z * xv.y;
            acc[3][0] += b03.w * xv.x; acc[3][1] += b03.w * xv.y;
            acc[4][0] += b47.x * xv.x; acc[4][1] += b47.x * xv.y;
            acc[5][0] += b47.y * xv.x; acc[5][1] += b47.y * xv.y;
            acc[6][0] += b47.z * xv.x; acc[6][1] += b47.z * xv.y;
            acc[7][0] += b47.w * xv.x; acc[7][1] += b47.w * xv.y;
            acc[8][0] += b8    * xv.x; acc[8][1] += b8    * xv.y;
        }

        #pragma unroll
        for (int k = 0; k < 9; k++) {
            uint32_t hi, lo;
            split2(acc[k][0], acc[k][1], hi, lo);
            int phys = (8 * k + (l >> 2)) ^ (r & 7);
            int off = r * ROWB + phys * 16 + (l & 3) * 4;
            *(uint32_t*)(sHi + off) = hi;
            *(uint32_t*)(sLo + off) = lo;
        }
    }
    __syncthreads();

    // ---- phase 3: warp w computes m16n8 tile, n-cols w*8 .. +7 ----
    const int lm_row = ((l >> 3) & 1) * 8 + (l & 7);
    const int lm_uh = l >> 4;
    const uint32_t sHiB = (uint32_t)__cvta_generic_to_shared(sHi);
    const uint32_t sLoB = (uint32_t)__cvta_generic_to_shared(sLo);

    float acc0[4] = {};
    #pragma unroll 4
    for (int kc = 0; kc < NKC; kc++) {
        int unit = 2 * kc + lm_uh;
        uint32_t soff = (uint32_t)(lm_row * ROWB + ((unit ^ (lm_row & 7)) << 4));
        uint32_t ah[4], al[4];
        ldsm4(ah, sHiB + soff);
        ldsm4(al, sLoB + soff);

        uint4 bf = __ldg(wfrag + (kc * 8 + w) * 32 + l);
        mma16816(acc0, ah[0], ah[1], ah[2], ah[3], bf.x, bf.y);
        mma16816(acc0, ah[0], ah[1], ah[2], ah[3], bf.z, bf.w);
        mma16816(acc0, al[0], al[1], al[2], al[3], bf.x, bf.y);
    }

    // ---- epilogue: bias + relu ----
    const int r0 = mbase + g, r1 = r0 + 8;
    const int c = w * 8 + t2;
    float b0 = __ldg(&bias[c]), b1 = __ldg(&bias[c + 1]);
    *(float2*)&H[(size_t)r0 * CH + c] =
        make_float2(fmaxf(acc0[0] + b0, 0.f), fmaxf(acc0[1] + b1, 0.f));
    *(float2*)&H[(size_t)r1 * CH + c] =
        make_float2(fmaxf(acc0[2] + b0, 0.f), fmaxf(acc0[3] + b1, 0.f));
}

// ---------------------------------------------------------------------------
extern "C" void kernel_launch(void* const* d_in, const int* in_sizes, int n_in,
                              void* d_out, int out_size) {
    const float* x      = (const float*)d_in[0];
    const int* ei32     = (const int*)d_in[1];
    const float* pseudo = (const float*)d_in[2];
    const float* W1     = (const float*)d_in[3];
    const float* root1  = (const float*)d_in[4];
    const float* b1     = (const float*)d_in[5];
    const float* W2     = (const float*)d_in[6];
    const float* root2  = (const float*)d_in[7];
    const float* b2     = (const float*)d_in[8];
    float* out          = (float*)d_out;

    cudaFuncSetAttribute(fused_layer_kernel<false>,
                         cudaFuncAttributeMaxDynamicSharedMemorySize, FSMEM);
    cudaFuncSetAttribute(fused_layer_kernel<true>,
                         cudaFuncAttributeMaxDynamicSharedMemorySize, FSMEM);

    // Launch 0: convert + histogram + weight prep
    convert_hist_wprep_kernel<<<CONV_BLOCKS + WPREP_BLOCKS, 256>>>(
        ei32, W1, root1, W2, root2);
    // Launch 1: single-pass scan (restores g_cnt/g_cur)
    scan_kernel<<<NSCAN_BLOCKS, SCAN_B>>>();
    // Launch 2: dst-sorted edge scatter + basis precompute
    scatter_kernel<<<(N_EDGES + 255) / 256, 256>>>(pseudo);
    // Launch 3 (profiled): fused layer 1
    fused_layer_kernel<false><<<FGRID, 256, FSMEM>>>(x, b1, nullptr);
    // Launch 4: fused layer 2
    fused_layer_kernel<true><<<FGRID, 256, FSMEM>>>(nullptr, b2, out);
}

// round 13
// speedup vs baseline: 2.2709x; 1.1603x over previous
#include <cuda_runtime.h>
#include <cuda_bf16.h>
#include <cstdint>

#define N_NODES 100000
#define N_EDGES 1600000
#define CH 64
#define TCOLS 576               // 9 * 64
#define KDIM 640                // 576 + 64
#define SCAN_B 1024
#define NSCAN_BLOCKS ((N_NODES + SCAN_B - 1) / SCAN_B)   // 98
#define NKC 40                  // K16 steps
#define NFRAG (NKC * 8 * 32)    // 10240 uint4 per layer
#define FM 16                   // nodes per fused block
#define FGRID (N_NODES / FM)    // 6250 (exact)
#define ROWU 80                 // 16B units per smem row (640 bf16)
#define ROWB (ROWU * 16)        // 1280 bytes
#define TILE_BYTES (FM * ROWB)  // 20480 per hi/lo
#define FSMEM (2 * TILE_BYTES)  // 40960
#define CONV_BLOCKS ((2 * N_EDGES + 255) / 256)   // 12500
#define WPREP_BLOCKS ((2 * NFRAG + 255) / 256)    // 80

// ------------------------- device scratch (no allocs) -----------------------
__device__ int     g_idx[2 * N_EDGES];
__device__ int     g_cnt[N_NODES];
__device__ int     g_cur[N_NODES];
__device__ int     g_row[N_NODES + 1];
__device__ int     g_bsum[NSCAN_BLOCKS];
__device__ int     g_ready;        // scan rendezvous; reset by scatter for next call
__device__ float4  g_edges[N_EDGES];   // {src(asint), u, v, pad} — 16 B
__device__ float   g_x2[(size_t)N_NODES * CH];
// Fragment-ready split-bf16 weights: [layer][kc][nt][lane] = {bh0,bh1,bl0,bl1}
__device__ uint4   g_wfrag[2][NFRAG];

// ------------------------------ helpers -------------------------------------
__device__ __forceinline__ uint32_t packbf2(float a, float b) {
    __nv_bfloat162 h;
    h.x = __float2bfloat16(a);
    h.y = __float2bfloat16(b);
    return *(uint32_t*)&h;
}

// hi = mantissa truncation of (x,y) packed bf16x2; lo = rn residual.
__device__ __forceinline__ void split2(float x, float y, uint32_t& hi, uint32_t& lo) {
    uint32_t u0 = __float_as_uint(x), u1 = __float_as_uint(y);
    asm("prmt.b32 %0, %1, %2, 0x7632;" : "=r"(hi) : "r"(u0), "r"(u1));
    float l0 = x - __uint_as_float(u0 & 0xFFFF0000u);
    float l1 = y - __uint_as_float(u1 & 0xFFFF0000u);
    asm("cvt.rn.bf16x2.f32 %0, %1, %2;" : "=r"(lo) : "f"(l1), "f"(l0));
}

__device__ __forceinline__ void mma16816(float* c,
    uint32_t a0, uint32_t a1, uint32_t a2, uint32_t a3, uint32_t b0, uint32_t b1)
{
    asm("mma.sync.aligned.m16n8k16.row.col.f32.bf16.bf16.f32 "
        "{%0,%1,%2,%3}, {%4,%5,%6,%7}, {%8,%9}, {%0,%1,%2,%3};"
        : "+f"(c[0]), "+f"(c[1]), "+f"(c[2]), "+f"(c[3])
        : "r"(a0), "r"(a1), "r"(a2), "r"(a3), "r"(b0), "r"(b1));
}

__device__ __forceinline__ void ldsm4(uint32_t* r, uint32_t saddr) {
    asm volatile("ldmatrix.sync.aligned.m8n8.x4.shared.b16 {%0,%1,%2,%3}, [%4];"
                 : "=r"(r[0]), "=r"(r[1]), "=r"(r[2]), "=r"(r[3]) : "r"(saddr));
}

// ---------------------------------------------------------------------------
// Launch 0: convert+histogram (inline dtype detection) + weight-fragment prep.
// ---------------------------------------------------------------------------
__global__ __launch_bounds__(256) void convert_hist_wprep_kernel(
    const int* __restrict__ ei32,
    const float* __restrict__ W1, const float* __restrict__ root1,
    const float* __restrict__ W2, const float* __restrict__ root2)
{
    const int b = blockIdx.x;
    if (b < CONV_BLOCKS) {
        __shared__ int s_is64;
        if (threadIdx.x < 32) {
            int ok = 1;
            for (int i = threadIdx.x * 2 + 1; i < 512; i += 64)
                if (ei32[i] != 0) ok = 0;
            ok = __all_sync(0xffffffffu, ok) ? 1 : 0;
            if (threadIdx.x == 0) s_is64 = ok;
        }
        __syncthreads();
        const int is64 = s_is64;

        int j = b * 256 + threadIdx.x;
        if (j < 2 * N_EDGES) {
            int v = is64 ? ei32[2 * j] : ei32[j];
            v = ((unsigned)v < (unsigned)N_NODES) ? v : 0;
            g_idx[j] = v;
            if (j >= N_EDGES) atomicAdd(&g_cnt[v], 1);
        }
    } else {
        int idx = (b - CONV_BLOCKS) * 256 + threadIdx.x;
        if (idx >= 2 * NFRAG) return;
        const int layer = idx >= NFRAG;
        const int fi = layer ? idx - NFRAG : idx;
        const float* W9   = layer ? W2 : W1;
        const float* root = layer ? root2 : root1;

        int l  = fi & 31;
        int nt = (fi >> 5) & 7;
        int kc = fi >> 8;
        int g = l >> 2, t2 = (l & 3) * 2;
        int n = nt * 8 + g;
        int k0 = kc * 16 + t2;

        float w[4];   // k0, k0+1, k0+8, k0+9
        #pragma unroll
        for (int j2 = 0; j2 < 4; j2++) {
            int kk = k0 + (j2 & 1) + (j2 >> 1) * 8;
            w[j2] = (kk < TCOLS) ? W9[kk * 64 + n] : root[(kk - TCOLS) * 64 + n];
        }
        uint32_t bh0 = packbf2(w[0], w[1]);
        uint32_t bh1 = packbf2(w[2], w[3]);
        __nv_bfloat162* h0 = (__nv_bfloat162*)&bh0;
        __nv_bfloat162* h1 = (__nv_bfloat162*)&bh1;
        uint32_t bl0 = packbf2(w[0] - __bfloat162float(h0->x), w[1] - __bfloat162float(h0->y));
        uint32_t bl1 = packbf2(w[2] - __bfloat162float(h1->x), w[3] - __bfloat162float(h1->y));
        g_wfrag[layer][fi] = make_uint4(bh0, bh1, bl0, bl1);
    }
}

// ---------------------------------------------------------------------------
// Launch 1: single-pass exclusive scan; restores g_cnt/g_cur for next call.
// ---------------------------------------------------------------------------
__global__ __launch_bounds__(SCAN_B) void scan_kernel() {
    __shared__ int s[SCAN_B];
    __shared__ int s_prev;
    const int t = threadIdx.x, b = blockIdx.x;
    const int i = b * SCAN_B + t;
    int v = (i < N_NODES) ? g_cnt[i] : 0;
    s[t] = v;
    __syncthreads();
    for (int off = 1; off < SCAN_B; off <<= 1) {
        int tmp = (t >= off) ? s[t - off] : 0;
        __syncthreads();
        s[t] += tmp;
        __syncthreads();
    }
    if (t == SCAN_B - 1) {
        g_bsum[b] = s[t];
        __threadfence();
        atomicAdd(&g_ready, 1);
    }
    if (t == 0) {
        while (*(volatile int*)&g_ready < NSCAN_BLOCKS) { }
        __threadfence();
        int p = 0;
        for (int q = 0; q < b; q++) p += __ldcg(&g_bsum[q]);
        s_prev = p;
    }
    __syncthreads();
    if (i < N_NODES) {
        g_row[i] = s_prev + s[t] - v;
        g_cnt[i] = 0;
        g_cur[i] = 0;
    }
    if (b == 0 && t == 0) g_row[N_NODES] = N_EDGES;
}

// ---------------------------------------------------------------------------
// Launch 2: dst-sorted scatter of compact {src,u,v} records; resets g_ready.
// ---------------------------------------------------------------------------
__global__ __launch_bounds__(256) void scatter_kernel(const float* __restrict__ pseudo) {
    if (blockIdx.x == 0 && threadIdx.x == 0) g_ready = 0;
    int e = blockIdx.x * 256 + threadIdx.x;
    if (e >= N_EDGES) return;
    int src = g_idx[e];
    int dst = g_idx[N_EDGES + e];
    float2 p = ((const float2*)pseudo)[e];

    int pos = g_row[dst] + atomicAdd(&g_cur[dst], 1);
    g_edges[pos] = make_float4(__int_as_float(src), p.x, p.y, 0.f);
}

// ---------------------------------------------------------------------------
// Launches 3,4: fused layer, FM=16 nodes/block.
//   phase 1: stage X rows (k=576..639) into smem hi/lo
//   phase 2: CSR aggregation (basis recomputed in-flight) -> smem t tile
//   phase 3: warp w computes m16n8 output tile n-cols w*8..w*8+7
// ---------------------------------------------------------------------------
template<bool LAYER2>
__global__ __launch_bounds__(256) void fused_layer_kernel(
    const float* __restrict__ Xext,
    const float* __restrict__ bias,
    float* __restrict__ Hext)
{
    extern __shared__ __align__(128) char smem[];
    char* sHi = smem;
    char* sLo = smem + TILE_BYTES;

    const float* X = LAYER2 ? g_x2 : Xext;
    float* H = LAYER2 ? Hext : g_x2;
    const uint4* wfrag = g_wfrag[LAYER2 ? 1 : 0];

    const int tid = threadIdx.x;
    const int w = tid >> 5, l = tid & 31;
    const int g = l >> 2, t2 = (l & 3) * 2;
    const int mbase = blockIdx.x * FM;

    // ---- phase 1: X rows -> cols 576..639 ----
    {
        int r = tid >> 4, cg = tid & 15;         // r 0..15, cg 0..15 (4 cols each)
        const float* xp = X + (size_t)(mbase + r) * CH + cg * 4;
        float4 v0 = *(const float4*)xp;
        uint32_t h0, l0, h1, l1;
        split2(v0.x, v0.y, h0, l0);
        split2(v0.z, v0.w, h1, l1);
        int phys = (72 + (cg >> 1)) ^ (r & 7);
        int off = r * ROWB + phys * 16 + (cg & 1) * 8;
        *(uint2*)(sHi + off) = make_uint2(h0, h1);
        *(uint2*)(sLo + off) = make_uint2(l0, l1);
    }

    // ---- phase 2: aggregation, warp w handles nodes mbase + w*2 .. +1 ----
    #pragma unroll
    for (int i = 0; i < 2; i++) {
        const int r = w * 2 + i;
        const int node = mbase + r;
        int beg = g_row[node], end = g_row[node + 1];
        float acc[9][2] = {};

        #pragma unroll 4
        for (int e = beg; e < end; e++) {
            float4 rec = __ldg(&g_edges[e]);
            int src = __float_as_int(rec.x);
            float u = rec.y, v = rec.z;
            float2 xv = __ldg((const float2*)&X[(size_t)src * CH + 2 * l]);

            // basis polynomials (quadratic B-spline), identical to reference
            float bu0 = 0.5f * u * u - u + 0.5f;
            float bu1 = -u * u + u + 0.5f;
            float bu2 = 0.5f * u * u;
            float bv0 = 0.5f * v * v - v + 0.5f;
            float bv1 = -v * v + v + 0.5f;
            float bv2 = 0.5f * v * v;

            // factored: s[a] = bu[a]*x; acc[3a+b] += bv[b]*s[a]
            float sx0 = bu0 * xv.x, sy0 = bu0 * xv.y;
            float sx1 = bu1 * xv.x, sy1 = bu1 * xv.y;
            float sx2 = bu2 * xv.x, sy2 = bu2 * xv.y;
            acc[0][0] += bv0 * sx0; acc[0][1] += bv0 * sy0;
            acc[1][0] += bv1 * sx0; acc[1][1] += bv1 * sy0;
            acc[2][0] += bv2 * sx0; acc[2][1] += bv2 * sy0;
            acc[3][0] += bv0 * sx1; acc[3][1] += bv0 * sy1;
            acc[4][0] += bv1 * sx1; acc[4][1] += bv1 * sy1;
            acc[5][0] += bv2 * sx1; acc[5][1] += bv2 * sy1;
            acc[6][0] += bv0 * sx2; acc[6][1] += bv0 * sy2;
            acc[7][0] += bv1 * sx2; acc[7][1] += bv1 * sy2;
            acc[8][0] += bv2 * sx2; acc[8][1] += bv2 * sy2;
        }

        #pragma unroll
        for (int k = 0; k < 9; k++) {
            uint32_t hi, lo;
            split2(acc[k][0], acc[k][1], hi, lo);
            int phys = (8 * k + (l >> 2)) ^ (r & 7);
            int off = r * ROWB + phys * 16 + (l & 3) * 4;
            *(uint32_t*)(sHi + off) = hi;
            *(uint32_t*)(sLo + off) = lo;
        }
    }
    __syncthreads();

    // ---- phase 3: warp w computes m16n8 tile, n-cols w*8 .. +7 ----
    const int lm_row = ((l >> 3) & 1) * 8 + (l & 7);
    const int lm_uh = l >> 4;
    const uint32_t sHiB = (uint32_t)__cvta_generic_to_shared(sHi);
    const uint32_t sLoB = (uint32_t)__cvta_generic_to_shared(sLo);

    float acc0[4] = {};
    #pragma unroll 4
    for (int kc = 0; kc < NKC; kc++) {
        int unit = 2 * kc + lm_uh;
        uint32_t soff = (uint32_t)(lm_row * ROWB + ((unit ^ (lm_row & 7)) << 4));
        uint32_t ah[4], al[4];
        ldsm4(ah, sHiB + soff);
        ldsm4(al, sLoB + soff);

        uint4 bf = __ldg(wfrag + (kc * 8 + w) * 32 + l);
        mma16816(acc0, ah[0], ah[1], ah[2], ah[3], bf.x, bf.y);
        mma16816(acc0, ah[0], ah[1], ah[2], ah[3], bf.z, bf.w);
        mma16816(acc0, al[0], al[1], al[2], al[3], bf.x, bf.y);
    }

    // ---- epilogue: bias + relu ----
    const int r0 = mbase + g, r1 = r0 + 8;
    const int c = w * 8 + t2;
    float b0 = __ldg(&bias[c]), b1 = __ldg(&bias[c + 1]);
    *(float2*)&H[(size_t)r0 * CH + c] =
        make_float2(fmaxf(acc0[0] + b0, 0.f), fmaxf(acc0[1] + b1, 0.f));
    *(float2*)&H[(size_t)r1 * CH + c] =
        make_float2(fmaxf(acc0[2] + b0, 0.f), fmaxf(acc0[3] + b1, 0.f));
}

// ---------------------------------------------------------------------------
extern "C" void kernel_launch(void* const* d_in, const int* in_sizes, int n_in,
                              void* d_out, int out_size) {
    const float* x      = (const float*)d_in[0];
    const int* ei32     = (const int*)d_in[1];
    const float* pseudo = (const float*)d_in[2];
    const float* W1     = (const float*)d_in[3];
    const float* root1  = (const float*)d_in[4];
    const float* b1     = (const float*)d_in[5];
    const float* W2     = (const float*)d_in[6];
    const float* root2  = (const float*)d_in[7];
    const float* b2     = (const float*)d_in[8];
    float* out          = (float*)d_out;

    cudaFuncSetAttribute(fused_layer_kernel<false>,
                         cudaFuncAttributeMaxDynamicSharedMemorySize, FSMEM);
    cudaFuncSetAttribute(fused_layer_kernel<true>,
                         cudaFuncAttributeMaxDynamicSharedMemorySize, FSMEM);

    // Launch 0: convert + histogram + weight prep
    convert_hist_wprep_kernel<<<CONV_BLOCKS + WPREP_BLOCKS, 256>>>(
        ei32, W1, root1, W2, root2);
    // Launch 1: single-pass scan (restores g_cnt/g_cur)
    scan_kernel<<<NSCAN_BLOCKS, SCAN_B>>>();
    // Launch 2: dst-sorted compact-edge scatter
    scatter_kernel<<<(N_EDGES + 255) / 256, 256>>>(pseudo);
    // Launch 3 (profiled): fused layer 1
    fused_layer_kernel<false><<<FGRID, 256, FSMEM>>>(x, b1, nullptr);
    // Launch 4: fused layer 2
    fused_layer_kernel<true><<<FGRID, 256, FSMEM>>>(nullptr, b2, out);
}

// round 14
// speedup vs baseline: 2.4751x; 1.0899x over previous
#include <cuda_runtime.h>
#include <cuda_bf16.h>
#include <cstdint>

#define N_NODES 100000
#define N_EDGES 1600000
#define CH 64
#define TCOLS 576               // 9 * 64
#define KDIM 640                // 576 + 64
#define SCAN_B 1024
#define NSCAN_BLOCKS ((N_NODES + SCAN_B - 1) / SCAN_B)   // 98
#define NKC 40                  // K16 steps
#define NFRAG (NKC * 8 * 32)    // 10240 uint4 per layer
#define FM 16                   // nodes per fused block
#define FGRID (N_NODES / FM)    // 6250 (exact)
#define ROWU 80                 // 16B units per smem row (640 bf16)
#define ROWB (ROWU * 16)        // 1280 bytes
#define TILE_BYTES (FM * ROWB)  // 20480 per hi/lo
#define FSMEM (2 * TILE_BYTES)  // 40960
#define CONV_BLOCKS ((2 * N_EDGES + 255) / 256)   // 12500
#define WPREP_BLOCKS ((2 * NFRAG + 255) / 256)    // 80

// ------------------------- device scratch (no allocs) -----------------------
__device__ int     g_idx[2 * N_EDGES];
__device__ int     g_cnt[N_NODES];
__device__ int     g_cur[N_NODES];
__device__ int     g_row[N_NODES + 1];
__device__ int     g_bsum[NSCAN_BLOCKS];
__device__ int     g_ready;        // scan rendezvous; reset by scatter for next call
__device__ float4  g_edges[N_EDGES];   // {src(asint), u, v, pad} — 16 B
__device__ float   g_x2[(size_t)N_NODES * CH];
// Fragment-ready split-bf16 weights: [layer][kc][nt][lane] = {bh0,bh1,bl0,bl1}
__device__ uint4   g_wfrag[2][NFRAG];

// ------------------------------ helpers -------------------------------------
__device__ __forceinline__ uint32_t packbf2(float a, float b) {
    __nv_bfloat162 h;
    h.x = __float2bfloat16(a);
    h.y = __float2bfloat16(b);
    return *(uint32_t*)&h;
}

// hi = mantissa truncation of (x,y) packed bf16x2; lo = rn residual.
__device__ __forceinline__ void split2(float x, float y, uint32_t& hi, uint32_t& lo) {
    uint32_t u0 = __float_as_uint(x), u1 = __float_as_uint(y);
    asm("prmt.b32 %0, %1, %2, 0x7632;" : "=r"(hi) : "r"(u0), "r"(u1));
    float l0 = x - __uint_as_float(u0 & 0xFFFF0000u);
    float l1 = y - __uint_as_float(u1 & 0xFFFF0000u);
    asm("cvt.rn.bf16x2.f32 %0, %1, %2;" : "=r"(lo) : "f"(l1), "f"(l0));
}

__device__ __forceinline__ void mma16816(float* c,
    uint32_t a0, uint32_t a1, uint32_t a2, uint32_t a3, uint32_t b0, uint32_t b1)
{
    asm("mma.sync.aligned.m16n8k16.row.col.f32.bf16.bf16.f32 "
        "{%0,%1,%2,%3}, {%4,%5,%6,%7}, {%8,%9}, {%0,%1,%2,%3};"
        : "+f"(c[0]), "+f"(c[1]), "+f"(c[2]), "+f"(c[3])
        : "r"(a0), "r"(a1), "r"(a2), "r"(a3), "r"(b0), "r"(b1));
}

__device__ __forceinline__ void ldsm4(uint32_t* r, uint32_t saddr) {
    asm volatile("ldmatrix.sync.aligned.m8n8.x4.shared.b16 {%0,%1,%2,%3}, [%4];"
                 : "=r"(r[0]), "=r"(r[1]), "=r"(r[2]), "=r"(r[3]) : "r"(saddr));
}

// ---------------------------------------------------------------------------
// Launch 0: convert+histogram (inline dtype detection) + weight-fragment prep.
// ---------------------------------------------------------------------------
__global__ __launch_bounds__(256) void convert_hist_wprep_kernel(
    const int* __restrict__ ei32,
    const float* __restrict__ W1, const float* __restrict__ root1,
    const float* __restrict__ W2, const float* __restrict__ root2)
{
    const int b = blockIdx.x;
    if (b < CONV_BLOCKS) {
        __shared__ int s_is64;
        if (threadIdx.x < 32) {
            int ok = 1;
            for (int i = threadIdx.x * 2 + 1; i < 512; i += 64)
                if (ei32[i] != 0) ok = 0;
            ok = __all_sync(0xffffffffu, ok) ? 1 : 0;
            if (threadIdx.x == 0) s_is64 = ok;
        }
        __syncthreads();
        const int is64 = s_is64;

        int j = b * 256 + threadIdx.x;
        if (j < 2 * N_EDGES) {
            int v = is64 ? ei32[2 * j] : ei32[j];
            v = ((unsigned)v < (unsigned)N_NODES) ? v : 0;
            g_idx[j] = v;
            if (j >= N_EDGES) atomicAdd(&g_cnt[v], 1);
        }
    } else {
        int idx = (b - CONV_BLOCKS) * 256 + threadIdx.x;
        if (idx >= 2 * NFRAG) return;
        const int layer = idx >= NFRAG;
        const int fi = layer ? idx - NFRAG : idx;
        const float* W9   = layer ? W2 : W1;
        const float* root = layer ? root2 : root1;

        int l  = fi & 31;
        int nt = (fi >> 5) & 7;
        int kc = fi >> 8;
        int g = l >> 2, t2 = (l & 3) * 2;
        int n = nt * 8 + g;
        int k0 = kc * 16 + t2;

        float w[4];   // k0, k0+1, k0+8, k0+9
        #pragma unroll
        for (int j2 = 0; j2 < 4; j2++) {
            int kk = k0 + (j2 & 1) + (j2 >> 1) * 8;
            w[j2] = (kk < TCOLS) ? W9[kk * 64 + n] : root[(kk - TCOLS) * 64 + n];
        }
        uint32_t bh0 = packbf2(w[0], w[1]);
        uint32_t bh1 = packbf2(w[2], w[3]);
        __nv_bfloat162* h0 = (__nv_bfloat162*)&bh0;
        __nv_bfloat162* h1 = (__nv_bfloat162*)&bh1;
        uint32_t bl0 = packbf2(w[0] - __bfloat162float(h0->x), w[1] - __bfloat162float(h0->y));
        uint32_t bl1 = packbf2(w[2] - __bfloat162float(h1->x), w[3] - __bfloat162float(h1->y));
        g_wfrag[layer][fi] = make_uint4(bh0, bh1, bl0, bl1);
    }
}

// ---------------------------------------------------------------------------
// Launch 1: single-pass exclusive scan; restores g_cnt/g_cur for next call.
// ---------------------------------------------------------------------------
__global__ __launch_bounds__(SCAN_B) void scan_kernel() {
    __shared__ int s[SCAN_B];
    __shared__ int s_prev;
    const int t = threadIdx.x, b = blockIdx.x;
    const int i = b * SCAN_B + t;
    int v = (i < N_NODES) ? g_cnt[i] : 0;
    s[t] = v;
    __syncthreads();
    for (int off = 1; off < SCAN_B; off <<= 1) {
        int tmp = (t >= off) ? s[t - off] : 0;
        __syncthreads();
        s[t] += tmp;
        __syncthreads();
    }
    if (t == SCAN_B - 1) {
        g_bsum[b] = s[t];
        __threadfence();
        atomicAdd(&g_ready, 1);
    }
    if (t == 0) {
        while (*(volatile int*)&g_ready < NSCAN_BLOCKS) { }
        __threadfence();
        int p = 0;
        for (int q = 0; q < b; q++) p += __ldcg(&g_bsum[q]);
        s_prev = p;
    }
    __syncthreads();
    if (i < N_NODES) {
        g_row[i] = s_prev + s[t] - v;
        g_cnt[i] = 0;
        g_cur[i] = 0;
    }
    if (b == 0 && t == 0) g_row[N_NODES] = N_EDGES;
}

// ---------------------------------------------------------------------------
// Launch 2: dst-sorted scatter of compact {src,u,v} records; resets g_ready.
// ---------------------------------------------------------------------------
__global__ __launch_bounds__(256) void scatter_kernel(const float* __restrict__ pseudo) {
    if (blockIdx.x == 0 && threadIdx.x == 0) g_ready = 0;
    int e = blockIdx.x * 256 + threadIdx.x;
    if (e >= N_EDGES) return;
    int src = g_idx[e];
    int dst = g_idx[N_EDGES + e];
    float2 p = ((const float2*)pseudo)[e];

    int pos = g_row[dst] + atomicAdd(&g_cur[dst], 1);
    g_edges[pos] = make_float4(__int_as_float(src), p.x, p.y, 0.f);
}

// ---------------------------------------------------------------------------
// Launches 3,4: fused layer, FM=16 nodes/block.
//   phase 1: stage X rows (k=576..639) into smem hi/lo
//   phase 2: CSR aggregation (basis recomputed in-flight) -> smem t tile
//   phase 3: 2-way k-split mma (warp = k-half x nt-pair) + smem reduction
// ---------------------------------------------------------------------------
template<bool LAYER2>
__global__ __launch_bounds__(256) void fused_layer_kernel(
    const float* __restrict__ Xext,
    const float* __restrict__ bias,
    float* __restrict__ Hext)
{
    extern __shared__ __align__(128) char smem[];
    char* sHi = smem;
    char* sLo = smem + TILE_BYTES;

    const float* X = LAYER2 ? g_x2 : Xext;
    float* H = LAYER2 ? Hext : g_x2;
    const uint4* wfrag = g_wfrag[LAYER2 ? 1 : 0];

    const int tid = threadIdx.x;
    const int w = tid >> 5, l = tid & 31;
    const int g = l >> 2, t2 = (l & 3) * 2;
    const int mbase = blockIdx.x * FM;

    // ---- phase 1: X rows -> cols 576..639 ----
    {
        int r = tid >> 4, cg = tid & 15;         // r 0..15, cg 0..15 (4 cols each)
        const float* xp = X + (size_t)(mbase + r) * CH + cg * 4;
        float4 v0 = *(const float4*)xp;
        uint32_t h0, l0, h1, l1;
        split2(v0.x, v0.y, h0, l0);
        split2(v0.z, v0.w, h1, l1);
        int phys = (72 + (cg >> 1)) ^ (r & 7);
        int off = r * ROWB + phys * 16 + (cg & 1) * 8;
        *(uint2*)(sHi + off) = make_uint2(h0, h1);
        *(uint2*)(sLo + off) = make_uint2(l0, l1);
    }

    // ---- phase 2: aggregation, warp w handles nodes mbase + w*2 .. +1 ----
    #pragma unroll
    for (int i = 0; i < 2; i++) {
        const int r = w * 2 + i;
        const int node = mbase + r;
        int beg = g_row[node], end = g_row[node + 1];
        float acc[9][2] = {};

        #pragma unroll 4
        for (int e = beg; e < end; e++) {
            float4 rec = __ldg(&g_edges[e]);
            int src = __float_as_int(rec.x);
            float u = rec.y, v = rec.z;
            float2 xv = __ldg((const float2*)&X[(size_t)src * CH + 2 * l]);

            // basis polynomials (quadratic B-spline), identical to reference
            float bu0 = 0.5f * u * u - u + 0.5f;
            float bu1 = -u * u + u + 0.5f;
            float bu2 = 0.5f * u * u;
            float bv0 = 0.5f * v * v - v + 0.5f;
            float bv1 = -v * v + v + 0.5f;
            float bv2 = 0.5f * v * v;

            // factored: s[a] = bu[a]*x; acc[3a+b] += bv[b]*s[a]
            float sx0 = bu0 * xv.x, sy0 = bu0 * xv.y;
            float sx1 = bu1 * xv.x, sy1 = bu1 * xv.y;
            float sx2 = bu2 * xv.x, sy2 = bu2 * xv.y;
            acc[0][0] += bv0 * sx0; acc[0][1] += bv0 * sy0;
            acc[1][0] += bv1 * sx0; acc[1][1] += bv1 * sy0;
            acc[2][0] += bv2 * sx0; acc[2][1] += bv2 * sy0;
            acc[3][0] += bv0 * sx1; acc[3][1] += bv0 * sy1;
            acc[4][0] += bv1 * sx1; acc[4][1] += bv1 * sy1;
            acc[5][0] += bv2 * sx1; acc[5][1] += bv2 * sy1;
            acc[6][0] += bv0 * sx2; acc[6][1] += bv0 * sy2;
            acc[7][0] += bv1 * sx2; acc[7][1] += bv1 * sy2;
            acc[8][0] += bv2 * sx2; acc[8][1] += bv2 * sy2;
        }

        #pragma unroll
        for (int k = 0; k < 9; k++) {
            uint32_t hi, lo;
            split2(acc[k][0], acc[k][1], hi, lo);
            int phys = (8 * k + (l >> 2)) ^ (r & 7);
            int off = r * ROWB + phys * 16 + (l & 3) * 4;
            *(uint32_t*)(sHi + off) = hi;
            *(uint32_t*)(sLo + off) = lo;
        }
    }
    __syncthreads();

    // ---- phase 3: warp (kh, np): k-range kh*20..+19, n-tiles 2np, 2np+1 ----
    const int kh = w >> 2, np = w & 3;
    const int lm_row = ((l >> 3) & 1) * 8 + (l & 7);
    const int lm_uh = l >> 4;
    const uint32_t sHiB = (uint32_t)__cvta_generic_to_shared(sHi);
    const uint32_t sLoB = (uint32_t)__cvta_generic_to_shared(sLo);

    float acc0[4] = {}, acc1[4] = {};
    #pragma unroll 4
    for (int kq = 0; kq < 20; kq++) {
        int kc = kh * 20 + kq;
        int unit = 2 * kc + lm_uh;
        uint32_t soff = (uint32_t)(lm_row * ROWB + ((unit ^ (lm_row & 7)) << 4));
        uint32_t ah[4], al[4];
        ldsm4(ah, sHiB + soff);
        ldsm4(al, sLoB + soff);

        uint4 bf0 = __ldg(wfrag + (kc * 8 + 2 * np) * 32 + l);
        uint4 bf1 = __ldg(wfrag + (kc * 8 + 2 * np + 1) * 32 + l);
        mma16816(acc0, ah[0], ah[1], ah[2], ah[3], bf0.x, bf0.y);
        mma16816(acc0, ah[0], ah[1], ah[2], ah[3], bf0.z, bf0.w);
        mma16816(acc0, al[0], al[1], al[2], al[3], bf0.x, bf0.y);
        mma16816(acc1, ah[0], ah[1], ah[2], ah[3], bf1.x, bf1.y);
        mma16816(acc1, ah[0], ah[1], ah[2], ah[3], bf1.z, bf1.w);
        mma16816(acc1, al[0], al[1], al[2], al[3], bf1.x, bf1.y);
    }

    // ---- cross-warp reduction: kh=1 partials -> smem -> kh=0 adds ----
    __syncthreads();                       // all ldsm reads of the tile done
    float* rb = (float*)sHi + np * 256 + l;   // 1KB per np, bank-conflict-free
    if (kh == 1) {
        #pragma unroll
        for (int j = 0; j < 4; j++) {
            rb[j * 32] = acc0[j];
            rb[(j + 4) * 32] = acc1[j];
        }
    }
    __syncthreads();
    if (kh == 0) {
        #pragma unroll
        for (int j = 0; j < 4; j++) {
            acc0[j] += rb[j * 32];
            acc1[j] += rb[(j + 4) * 32];
        }

        // ---- epilogue: bias + relu for n-tiles 2np, 2np+1 ----
        const int r0 = mbase + g, r1 = r0 + 8;
        const int c0 = (2 * np) * 8 + t2;
        const int c1 = (2 * np + 1) * 8 + t2;
        float b00 = __ldg(&bias[c0]), b01 = __ldg(&bias[c0 + 1]);
        float b10 = __ldg(&bias[c1]), b11 = __ldg(&bias[c1 + 1]);
        *(float2*)&H[(size_t)r0 * CH + c0] =
            make_float2(fmaxf(acc0[0] + b00, 0.f), fmaxf(acc0[1] + b01, 0.f));
        *(float2*)&H[(size_t)r1 * CH + c0] =
            make_float2(fmaxf(acc0[2] + b00, 0.f), fmaxf(acc0[3] + b01, 0.f));
        *(float2*)&H[(size_t)r0 * CH + c1] =
            make_float2(fmaxf(acc1[0] + b10, 0.f), fmaxf(acc1[1] + b11, 0.f));
        *(float2*)&H[(size_t)r1 * CH + c1] =
            make_float2(fmaxf(acc1[2] + b10, 0.f), fmaxf(acc1[3] + b11, 0.f));
    }
}

// ---------------------------------------------------------------------------
extern "C" void kernel_launch(void* const* d_in, const int* in_sizes, int n_in,
                              void* d_out, int out_size) {
    const float* x      = (const float*)d_in[0];
    const int* ei32     = (const int*)d_in[1];
    const float* pseudo = (const float*)d_in[2];
    const float* W1     = (const float*)d_in[3];
    const float* root1  = (const float*)d_in[4];
    const float* b1     = (const float*)d_in[5];
    const float* W2     = (const float*)d_in[6];
    const float* root2  = (const float*)d_in[7];
    const float* b2     = (const float*)d_in[8];
    float* out          = (float*)d_out;

    cudaFuncSetAttribute(fused_layer_kernel<false>,
                         cudaFuncAttributeMaxDynamicSharedMemorySize, FSMEM);
    cudaFuncSetAttribute(fused_layer_kernel<true>,
                         cudaFuncAttributeMaxDynamicSharedMemorySize, FSMEM);

    // Launch 0: convert + histogram + weight prep
    convert_hist_wprep_kernel<<<CONV_BLOCKS + WPREP_BLOCKS, 256>>>(
        ei32, W1, root1, W2, root2);
    // Launch 1: single-pass scan (restores g_cnt/g_cur)
    scan_kernel<<<NSCAN_BLOCKS, SCAN_B>>>();
    // Launch 2: dst-sorted compact-edge scatter
    scatter_kernel<<<(N_EDGES + 255) / 256, 256>>>(pseudo);
    // Launch 3 (profiled): fused layer 1
    fused_layer_kernel<false><<<FGRID, 256, FSMEM>>>(x, b1, nullptr);
    // Launch 4: fused layer 2
    fused_layer_kernel<true><<<FGRID, 256, FSMEM>>>(nullptr, b2, out);
}